// round 7
// baseline (speedup 1.0000x reference)
#include <cuda_runtime.h>
#include <cuda_bf16.h>
#include <cstdint>

#define IN_DIM  2048
#define HDIM    8192
#define OUT_DIM 512
#define NBATCH  4096

typedef __nv_bfloat16 bf16;

// ---------------- scratch (static __device__ per harness rules) ----------------
__device__ __align__(256) bf16 g_xhi [(size_t)NBATCH * IN_DIM];
__device__ __align__(256) bf16 g_xlo [(size_t)NBATCH * IN_DIM];
__device__ __align__(256) bf16 g_W1hi[(size_t)IN_DIM * HDIM];
__device__ __align__(256) bf16 g_W1lo[(size_t)IN_DIM * HDIM];
__device__ __align__(256) bf16 g_W1Thi[(size_t)HDIM * IN_DIM];
__device__ __align__(256) bf16 g_W1Tlo[(size_t)HDIM * IN_DIM];
__device__ __align__(256) bf16 g_W2hi[(size_t)HDIM * OUT_DIM];
__device__ __align__(256) bf16 g_W2lo[(size_t)HDIM * OUT_DIM];
__device__ __align__(256) bf16 g_W2Thi[(size_t)OUT_DIM * HDIM];
__device__ __align__(256) bf16 g_W2Tlo[(size_t)OUT_DIM * HDIM];
__device__ __align__(256) bf16 g_z1hi[(size_t)NBATCH * HDIM];
__device__ __align__(256) bf16 g_z1lo[(size_t)NBATCH * HDIM];
__device__ __align__(256) bf16 g_zhi [(size_t)NBATCH * OUT_DIM];
__device__ __align__(256) bf16 g_zlo [(size_t)NBATCH * OUT_DIM];
__device__ __align__(256) bf16 g_thi [(size_t)NBATCH * HDIM];
__device__ __align__(256) bf16 g_tlo [(size_t)NBATCH * HDIM];
__device__ int g_maskmode;

// ---------------- PTX helpers (compute_100-safe) ----------------
__device__ __forceinline__ uint32_t smem_u32(const void* p) {
    uint32_t a;
    asm("{ .reg .u64 t; cvta.to.shared.u64 t, %1; cvt.u32.u64 %0, t; }" : "=r"(a) : "l"(p));
    return a;
}
#define SWZ128(off) ((off) ^ (((off) >> 3) & 0x70))

__device__ __forceinline__ void cp16(uint32_t dst, const void* src) {
    asm volatile("cp.async.cg.shared.global [%0], [%1], 16;" :: "r"(dst), "l"(src));
}
#define CP_COMMIT() asm volatile("cp.async.commit_group;" ::: "memory")
#define CP_WAIT(n)  asm volatile("cp.async.wait_group %0;" :: "n"(n) : "memory")

__device__ __forceinline__ void ldsm4(uint32_t a, uint32_t& r0, uint32_t& r1,
                                      uint32_t& r2, uint32_t& r3) {
    asm volatile("ldmatrix.sync.aligned.m8n8.x4.shared.b16 {%0,%1,%2,%3}, [%4];"
                 : "=r"(r0), "=r"(r1), "=r"(r2), "=r"(r3) : "r"(a));
}

__device__ __forceinline__ void mma16816(float* d, const uint32_t* a, const uint32_t* b) {
    asm volatile("mma.sync.aligned.m16n8k16.row.col.f32.bf16.bf16.f32 "
        "{%0,%1,%2,%3}, {%4,%5,%6,%7}, {%8,%9}, {%0,%1,%2,%3};"
        : "+f"(d[0]), "+f"(d[1]), "+f"(d[2]), "+f"(d[3])
        : "r"(a[0]), "r"(a[1]), "r"(a[2]), "r"(a[3]), "r"(b[0]), "r"(b[1]));
}

// ---------------- mask dtype detection ----------------
__global__ void detect_mask_kernel(const unsigned int* __restrict__ m, int nwords) {
    __shared__ int ok[4];
    if (threadIdx.x < 4) ok[threadIdx.x] = 1;
    __syncthreads();
    for (int i = threadIdx.x; i < nwords; i += blockDim.x) {
        unsigned w = m[i];
        if (!(w == 0u || w == 1u))          atomicAnd(&ok[0], 0);
        if (!(w == 0u || w == 0x3F800000u)) atomicAnd(&ok[1], 0);
        unsigned lo = w & 0xFFFFu, hi = w >> 16;
        if (!((lo == 0u || lo == 0x3F80u) && (hi == 0u || hi == 0x3F80u))) atomicAnd(&ok[2], 0);
        if (!((lo == 0u || lo == 0x3C00u) && (hi == 0u || hi == 0x3C00u))) atomicAnd(&ok[3], 0);
    }
    __syncthreads();
    if (threadIdx.x == 0) {
        int mode = 0;
        if      (ok[0]) mode = 1;
        else if (ok[1]) mode = 2;
        else if (ok[2]) mode = 3;
        else if (ok[3]) mode = 4;
        g_maskmode = mode;
    }
}

__device__ __forceinline__ int read_mask(const void* p, long i, int mode) {
    switch (mode) {
        case 1:  return ((const int*)p)[i] != 0;
        case 2:  return ((const float*)p)[i] != 0.0f;
        case 3:  return ((const unsigned short*)p)[i] != 0;
        case 4:  return ((const unsigned short*)p)[i] != 0;
        default: return ((const unsigned char*)p)[i] != 0;
    }
}

__device__ __forceinline__ void split2(float v, bf16& h, bf16& l) {
    h = __float2bfloat16(v);
    l = __float2bfloat16(v - __bfloat162float(h));
}

// ---------------- split x ----------------
__global__ void split_kernel(const float* __restrict__ src, bf16* __restrict__ hi,
                             bf16* __restrict__ lo, size_t n) {
    size_t i = (size_t)blockIdx.x * blockDim.x + threadIdx.x;
    if (i < n) {
        bf16 h, l;
        split2(src[i], h, l);
        hi[i] = h; lo[i] = l;
    }
}

// ---------------- dequant + split + transpose ----------------
__global__ void dequant_split_kernel(const int* __restrict__ idx, const void* __restrict__ mask,
                                     const float* __restrict__ wf, const float* __restrict__ cb,
                                     bf16* __restrict__ Whi, bf16* __restrict__ Wlo,
                                     bf16* __restrict__ WThi, bf16* __restrict__ WTlo,
                                     int R, int C) {
    __shared__ float tile[32][33];
    const int mode = g_maskmode;
    const int c0 = blockIdx.x * 32;
    const int r0 = blockIdx.y * 32;
    for (int rr = threadIdx.y; rr < 32; rr += 8) {
        long off = (long)(r0 + rr) * C + c0 + threadIdx.x;
        int  m = read_mask(mask, off, mode);
        float v = m ? cb[idx[off]] : wf[off];
        bf16 h, l; split2(v, h, l);
        Whi[off] = h; Wlo[off] = l;
        tile[rr][threadIdx.x] = v;
    }
    __syncthreads();
    for (int rr = threadIdx.y; rr < 32; rr += 8) {
        float v = tile[threadIdx.x][rr];
        long off = (long)(c0 + rr) * R + r0 + threadIdx.x;
        bf16 h, l; split2(v, h, l);
        WThi[off] = h; WTlo[off] = l;
    }
}

// ---------------- c19 activation ----------------
__device__ __forceinline__ float c19f(float x, float craw, float rhoraw) {
    float c   = fmaxf(craw, 0.1f);
    float rho = fmaxf(rhoraw, 0.0f);
    float L   = 6.0f * c;
    float s   = x / c;
    float n   = floorf(s);
    float t   = s - n;
    float h   = t * (1.0f - t);
    float sgn = (fmodf(n, 2.0f) == 0.0f) ? 1.0f : -1.0f;
    float interior = c * (sgn * h + rho * h * h);
    return (x >= L) ? (x - L) : ((x <= -L) ? (x + L) : interior);
}

// ---------------- mma.sync split-bf16 GEMM (pipelined frags) ----------------
// C[M,Nn] = sum over 3 passes A_p[M,K] * B_p[Nn,K]^T  (B K-major)
// passes: (Ahi,Bhi), (Ahi,Blo), (Alo,Bhi)
// Block 128 x (NI*32). 8 warps: 2(M) x 4(N); warp tile 64 x (NI*8). BK=32.
// NSTAGE=5 with wait_group(2): stages it AND it+1 resident -> cross-iteration
// register-level fragment prefetch (LDSM latency hidden behind MMA issue).
#define BM 128
#define BKK 32
#define NSTAGE 5

template<int NI>   // warp N-tile = NI*8, block N = NI*32.  NI=8 -> 256, NI=4 -> 128
__global__ void __launch_bounds__(256, 1)
gemm_split_kernel(const bf16* __restrict__ Ahi, const bf16* __restrict__ Alo,
                  const bf16* __restrict__ Bhi, const bf16* __restrict__ Blo,
                  int M, int Nn, int K,
                  const float* __restrict__ bias, int epi,
                  const float* __restrict__ craw, const float* __restrict__ rho,
                  float* __restrict__ Cf, bf16* __restrict__ Chi, bf16* __restrict__ Clo) {
    constexpr int BN = NI * 32;
    constexpr int STAGE_BYTES = BM * 64 + BN * 64;
    extern __shared__ char smem[];
    const uint32_t sbase = smem_u32(smem);
    const uint32_t tbase = (sbase + 1023u) & ~1023u;   // 1024B align for swizzle
    const int tid  = threadIdx.x;
    const int wid  = tid >> 5;
    const int lane = tid & 31;
    const int wm = wid & 1;          // M offset wm*64
    const int wn = wid >> 1;         // N offset wn*(NI*8)

    const int m0 = blockIdx.y * BM;
    const int n0 = blockIdx.x * BN;

    uint32_t sA[NSTAGE], sB[NSTAGE];
#pragma unroll
    for (int s = 0; s < NSTAGE; s++) {
        sA[s] = tbase + s * STAGE_BYTES;
        sB[s] = sA[s] + BM * 64;
    }

    const int kchunks = K / BKK;
    const int ITERS = 3 * kchunks;

    float acc[4][NI][4];
#pragma unroll
    for (int i = 0; i < 4; i++)
#pragma unroll
        for (int j = 0; j < NI; j++)
#pragma unroll
            for (int r = 0; r < 4; r++) acc[i][j][r] = 0.0f;

    auto fill = [&](int it) {
        const int p  = it / kchunks;
        const int kc = it % kchunks;
        const bf16* Ap = (p == 2) ? Alo : Ahi;
        const bf16* Bp = (p == 1) ? Blo : Bhi;
        const int s = it % NSTAGE;
        const size_t k0 = (size_t)kc * BKK;
#pragma unroll
        for (int i = 0; i < 2; i++) {
            int ch = tid + i * 256;
            int r = ch >> 2, c = ch & 3;
            const char* srcA = (const char*)(Ap + (size_t)(m0 + r) * K + k0) + c * 16;
            cp16(sA[s] + SWZ128(r * 64 + c * 16), srcA);
        }
#pragma unroll
        for (int i = 0; i < NI / 2; i++) {
            int ch = tid + i * 256;
            int r = ch >> 2, c = ch & 3;
            const char* srcB = (const char*)(Bp + (size_t)(n0 + r) * K + k0) + c * 16;
            cp16(sB[s] + SWZ128(r * 64 + c * 16), srcB);
        }
    };

    // register frag double buffers
    uint32_t af[2][4][4];
    uint32_t bfr[2][NI][2];

    auto load_frags = [&](int b, uint32_t Ab, uint32_t Bb, int kk) {
#pragma unroll
        for (int mi = 0; mi < 4; mi++) {
            int row = wm * 64 + mi * 16 + (lane & 15);
            int ch  = kk * 2 + (lane >> 4);
            ldsm4(Ab + SWZ128(row * 64 + ch * 16),
                  af[b][mi][0], af[b][mi][1], af[b][mi][2], af[b][mi][3]);
        }
#pragma unroll
        for (int p = 0; p < NI / 2; p++) {
            int g   = lane >> 3;
            int ni  = p * 2 + (g >> 1);
            int row = wn * (NI * 8) + ni * 8 + (lane & 7);
            int ch  = kk * 2 + (g & 1);
            uint32_t r0, r1, r2, r3;
            ldsm4(Bb + SWZ128(row * 64 + ch * 16), r0, r1, r2, r3);
            bfr[b][p * 2][0] = r0;  bfr[b][p * 2][1] = r1;
            bfr[b][p * 2 + 1][0] = r2; bfr[b][p * 2 + 1][1] = r3;
        }
    };

    auto mma_all = [&](int b) {
#pragma unroll
        for (int mi = 0; mi < 4; mi++)
#pragma unroll
            for (int ni = 0; ni < NI; ni++)
                mma16816(acc[mi][ni], af[b][mi], bfr[b][ni]);
    };

    // prologue: fill stages 0..3 (4 commit groups)
    for (int it = 0; it < NSTAGE - 1; it++) { fill(it); CP_COMMIT(); }
    CP_WAIT(3);                 // stage 0 ready
    __syncthreads();
    load_frags(0, sA[0], sB[0], 0);   // frags(it=0, kk=0) -> buf 0

    for (int it = 0; it < ITERS; it++) {
        CP_WAIT(2);             // stages it and it+1 both ready
        __syncthreads();        // all warps done reading the stage fill() overwrites
        if (it + NSTAGE - 1 < ITERS) fill(it + NSTAGE - 1);
        CP_COMMIT();

        const int s  = it % NSTAGE;
        const int s1 = (it + 1) % NSTAGE;

        // kk=0: prefetch kk=1 frags into buf1, MMA on buf0
        load_frags(1, sA[s], sB[s], 1);
        mma_all(0);
        // kk=1: prefetch next-iteration kk=0 frags into buf0, MMA on buf1
        if (it + 1 < ITERS) load_frags(0, sA[s1], sB[s1], 0);
        mma_all(1);
    }

    // ---------------- epilogue: bias (+c19) + outputs ----------------
#pragma unroll
    for (int ni = 0; ni < NI; ni++) {
        const int n = n0 + wn * (NI * 8) + ni * 8 + 2 * (lane & 3);
        const float bv0 = __ldg(bias + n), bv1 = __ldg(bias + n + 1);
        float c0 = 0, c1 = 0, r0 = 0, r1 = 0;
        if (epi) {
            c0 = __ldg(craw + n);  c1 = __ldg(craw + n + 1);
            r0 = __ldg(rho + n);   r1 = __ldg(rho + n + 1);
        }
#pragma unroll
        for (int mi = 0; mi < 4; mi++) {
#pragma unroll
            for (int h = 0; h < 2; h++) {
                const int m = m0 + wm * 64 + mi * 16 + (lane >> 2) + h * 8;
                float v0 = acc[mi][ni][2 * h]     + bv0;
                float v1 = acc[mi][ni][2 * h + 1] + bv1;
                if (epi) { v0 = c19f(v0, c0, r0); v1 = c19f(v1, c1, r1); }
                const size_t off = (size_t)m * Nn + n;
                if (Cf) *(float2*)(Cf + off) = make_float2(v0, v1);
                if (Chi) {
                    bf16 h0, l0, h1, l1;
                    split2(v0, h0, l0); split2(v1, h1, l1);
                    *(__nv_bfloat162*)(Chi + off) = __nv_bfloat162(h0, h1);
                    *(__nv_bfloat162*)(Clo + off) = __nv_bfloat162(l0, l1);
                }
            }
        }
    }
}

#define SMEM_FOR(NI) (1024 + NSTAGE * (BM * 64 + (NI) * 32 * 64))

// ---------------- launch ----------------
extern "C" void kernel_launch(void* const* d_in, const int* in_sizes, int n_in,
                              void* d_out, int out_size) {
    const float* x    = (const float*)d_in[0];
    const float* cb1  = (const float*)d_in[1];
    const float* cb2  = (const float*)d_in[2];
    const float* W1f  = (const float*)d_in[3];
    const float* W2f  = (const float*)d_in[4];
    const float* b1   = (const float*)d_in[5];
    const float* b2   = (const float*)d_in[6];
    const float* db1  = (const float*)d_in[7];
    const float* db2  = (const float*)d_in[8];
    const float* craw = (const float*)d_in[9];
    const float* rraw = (const float*)d_in[10];
    const int*   W1i  = (const int*)d_in[11];
    const int*   W2i  = (const int*)d_in[12];
    const void*  W1m  = d_in[13];
    const void*  W2m  = d_in[14];

    bf16 *xhi, *xlo, *W1hi, *W1lo, *W1Thi, *W1Tlo, *W2hi, *W2lo, *W2Thi, *W2Tlo;
    bf16 *z1hi, *z1lo, *zhi, *zlo, *thi, *tlo;
    cudaGetSymbolAddress((void**)&xhi,  g_xhi);   cudaGetSymbolAddress((void**)&xlo,  g_xlo);
    cudaGetSymbolAddress((void**)&W1hi, g_W1hi);  cudaGetSymbolAddress((void**)&W1lo, g_W1lo);
    cudaGetSymbolAddress((void**)&W1Thi,g_W1Thi); cudaGetSymbolAddress((void**)&W1Tlo,g_W1Tlo);
    cudaGetSymbolAddress((void**)&W2hi, g_W2hi);  cudaGetSymbolAddress((void**)&W2lo, g_W2lo);
    cudaGetSymbolAddress((void**)&W2Thi,g_W2Thi); cudaGetSymbolAddress((void**)&W2Tlo,g_W2Tlo);
    cudaGetSymbolAddress((void**)&z1hi, g_z1hi);  cudaGetSymbolAddress((void**)&z1lo, g_z1lo);
    cudaGetSymbolAddress((void**)&zhi,  g_zhi);   cudaGetSymbolAddress((void**)&zlo,  g_zlo);
    cudaGetSymbolAddress((void**)&thi,  g_thi);   cudaGetSymbolAddress((void**)&tlo,  g_tlo);

    float* dec = (float*)d_out;
    float* z   = (float*)d_out + (size_t)NBATCH * IN_DIM;

    cudaFuncSetAttribute(gemm_split_kernel<8>,
                         cudaFuncAttributeMaxDynamicSharedMemorySize, SMEM_FOR(8));
    cudaFuncSetAttribute(gemm_split_kernel<4>,
                         cudaFuncAttributeMaxDynamicSharedMemorySize, SMEM_FOR(4));

    // 1. mask dtype probe
    detect_mask_kernel<<<1, 256>>>((const unsigned int*)W1m, 4096);

    // 2. split x, dequant+split weights (with transposes)
    {
        size_t n = (size_t)NBATCH * IN_DIM;
        split_kernel<<<(unsigned)((n + 255) / 256), 256>>>(x, xhi, xlo, n);
    }
    dequant_split_kernel<<<dim3(HDIM / 32, IN_DIM / 32), dim3(32, 8)>>>(
        W1i, W1m, W1f, cb1, W1hi, W1lo, W1Thi, W1Tlo, IN_DIM, HDIM);
    dequant_split_kernel<<<dim3(OUT_DIM / 32, HDIM / 32), dim3(32, 8)>>>(
        W2i, W2m, W2f, cb2, W2hi, W2lo, W2Thi, W2Tlo, HDIM, OUT_DIM);

    // 3. G1: z1 = c19(x @ W1 + b1)  -> split bf16 only   [4096 x 8192]
    gemm_split_kernel<8><<<dim3(HDIM / 256, NBATCH / BM), 256, SMEM_FOR(8)>>>(
        xhi, xlo, W1Thi, W1Tlo, NBATCH, HDIM, IN_DIM,
        b1, 1, craw, rraw, nullptr, z1hi, z1lo);

    // 4. G2: z = z1 @ W2 + b2  -> fp32 output + split    [4096 x 512]
    gemm_split_kernel<4><<<dim3(OUT_DIM / 128, NBATCH / BM), 256, SMEM_FOR(4)>>>(
        z1hi, z1lo, W2Thi, W2Tlo, NBATCH, OUT_DIM, HDIM,
        b2, 0, nullptr, nullptr, z, zhi, zlo);

    // 5. G3: t = z @ W2^T + db1  -> split only           [4096 x 8192]
    gemm_split_kernel<8><<<dim3(HDIM / 256, NBATCH / BM), 256, SMEM_FOR(8)>>>(
        zhi, zlo, W2hi, W2lo, NBATCH, HDIM, OUT_DIM,
        db1, 0, nullptr, nullptr, nullptr, thi, tlo);

    // 6. G4: dec = t @ W1^T + db2  -> fp32 output        [4096 x 2048]
    gemm_split_kernel<8><<<dim3(IN_DIM / 256, NBATCH / BM), 256, SMEM_FOR(8)>>>(
        thi, tlo, W1hi, W1lo, NBATCH, IN_DIM, HDIM,
        db2, 0, nullptr, nullptr, dec, nullptr, nullptr);
}

// round 9
// speedup vs baseline: 1.3323x; 1.3323x over previous
#include <cuda_runtime.h>
#include <cuda_fp16.h>
#include <cstdint>

#define IN_DIM  2048
#define HDIM    8192
#define OUT_DIM 512
#define NBATCH  4096

typedef __half fp16;

// ---------------- scratch (static __device__ per harness rules) ----------------
__device__ __align__(256) fp16 g_xhi [(size_t)NBATCH * IN_DIM];
__device__ __align__(256) fp16 g_xlo [(size_t)NBATCH * IN_DIM];
__device__ __align__(256) fp16 g_W1hi[(size_t)IN_DIM * HDIM];     // Ŵ1 = W1/s1
__device__ __align__(256) fp16 g_W1Thi[(size_t)HDIM * IN_DIM];
__device__ __align__(256) fp16 g_W1Tlo[(size_t)HDIM * IN_DIM];
__device__ __align__(256) fp16 g_W2hi[(size_t)HDIM * OUT_DIM];    // Ŵ2 = W2/s2
__device__ __align__(256) fp16 g_W2Thi[(size_t)OUT_DIM * HDIM];
__device__ __align__(256) fp16 g_z1hi[(size_t)NBATCH * HDIM];
__device__ __align__(256) fp16 g_z1lo[(size_t)NBATCH * HDIM];
__device__ __align__(256) fp16 g_zhi [(size_t)NBATCH * OUT_DIM];
__device__ __align__(256) fp16 g_zlo [(size_t)NBATCH * OUT_DIM];
__device__ __align__(256) fp16 g_thi [(size_t)NBATCH * HDIM];
__device__ __align__(256) fp16 g_tlo [(size_t)NBATCH * HDIM];
__device__ int g_maskmode;

// ---------------- PTX helpers (compute_100-safe) ----------------
__device__ __forceinline__ uint32_t smem_u32(const void* p) {
    uint32_t a;
    asm("{ .reg .u64 t; cvta.to.shared.u64 t, %1; cvt.u32.u64 %0, t; }" : "=r"(a) : "l"(p));
    return a;
}
#define SWZ128(off) ((off) ^ (((off) >> 3) & 0x70))

__device__ __forceinline__ void cp16cp(uint32_t dst, const void* src) {
    asm volatile("cp.async.cg.shared.global [%0], [%1], 16;" :: "r"(dst), "l"(src));
}
#define CP_COMMIT() asm volatile("cp.async.commit_group;" ::: "memory")
#define CP_WAIT(n)  asm volatile("cp.async.wait_group %0;" :: "n"(n) : "memory")

__device__ __forceinline__ void ldsm4(uint32_t a, uint32_t& r0, uint32_t& r1,
                                      uint32_t& r2, uint32_t& r3) {
    asm volatile("ldmatrix.sync.aligned.m8n8.x4.shared.b16 {%0,%1,%2,%3}, [%4];"
                 : "=r"(r0), "=r"(r1), "=r"(r2), "=r"(r3) : "r"(a));
}

__device__ __forceinline__ void mma16816(float* d, const uint32_t* a, const uint32_t* b) {
    asm volatile("mma.sync.aligned.m16n8k16.row.col.f32.f16.f16.f32 "
        "{%0,%1,%2,%3}, {%4,%5,%6,%7}, {%8,%9}, {%0,%1,%2,%3};"
        : "+f"(d[0]), "+f"(d[1]), "+f"(d[2]), "+f"(d[3])
        : "r"(a[0]), "r"(a[1]), "r"(a[2]), "r"(a[3]), "r"(b[0]), "r"(b[1]));
}

// ---------------- mask dtype detection ----------------
__global__ void detect_mask_kernel(const unsigned int* __restrict__ m, int nwords) {
    __shared__ int ok[4];
    if (threadIdx.x < 4) ok[threadIdx.x] = 1;
    __syncthreads();
    for (int i = threadIdx.x; i < nwords; i += blockDim.x) {
        unsigned w = m[i];
        if (!(w == 0u || w == 1u))          atomicAnd(&ok[0], 0);
        if (!(w == 0u || w == 0x3F800000u)) atomicAnd(&ok[1], 0);
        unsigned lo = w & 0xFFFFu, hi = w >> 16;
        if (!((lo == 0u || lo == 0x3F80u) && (hi == 0u || hi == 0x3F80u))) atomicAnd(&ok[2], 0);
        if (!((lo == 0u || lo == 0x3C00u) && (hi == 0u || hi == 0x3C00u))) atomicAnd(&ok[3], 0);
    }
    __syncthreads();
    if (threadIdx.x == 0) {
        int mode = 0;
        if      (ok[0]) mode = 1;
        else if (ok[1]) mode = 2;
        else if (ok[2]) mode = 3;
        else if (ok[3]) mode = 4;
        g_maskmode = mode;
    }
}

__device__ __forceinline__ int read_mask(const void* p, long i, int mode) {
    switch (mode) {
        case 1:  return ((const int*)p)[i] != 0;
        case 2:  return ((const float*)p)[i] != 0.0f;
        case 3:  return ((const unsigned short*)p)[i] != 0;
        case 4:  return ((const unsigned short*)p)[i] != 0;
        default: return ((const unsigned char*)p)[i] != 0;
    }
}

__device__ __forceinline__ void split2h(float v, fp16& h, fp16& l) {
    h = __float2half(v);
    l = __float2half(v - __half2float(h));
}

// ---------------- split x (fp16 hi/lo) ----------------
__global__ void split_kernel(const float* __restrict__ src, fp16* __restrict__ hi,
                             fp16* __restrict__ lo, size_t n) {
    size_t i = (size_t)blockIdx.x * blockDim.x + threadIdx.x;
    if (i < n) {
        fp16 h, l;
        split2h(src[i], h, l);
        hi[i] = h; lo[i] = l;
    }
}

// ---------------- dequant + scale-factor + split + transpose ----------------
// vhat = (mask ? cb[idx] : wf) / s  with s = cb[3] (exact for codebook entries)
// WTlo may be nullptr (transposed lo-residual not needed).
__global__ void dequant_split_kernel(const int* __restrict__ idx, const void* __restrict__ mask,
                                     const float* __restrict__ wf, const float* __restrict__ cb,
                                     fp16* __restrict__ Whi,
                                     fp16* __restrict__ WThi, fp16* __restrict__ WTlo,
                                     int R, int C) {
    __shared__ float tile[32][33];
    const int mode = g_maskmode;
    float s = __ldg(cb + 3);
    if (s == 0.0f) s = 1.0f;
    const int c0 = blockIdx.x * 32;
    const int r0 = blockIdx.y * 32;
    for (int rr = threadIdx.y; rr < 32; rr += 8) {
        long off = (long)(r0 + rr) * C + c0 + threadIdx.x;
        int  m = read_mask(mask, off, mode);
        float v = (m ? cb[idx[off]] : wf[off]) / s;   // exact for codebook
        Whi[off] = __float2half(v);
        tile[rr][threadIdx.x] = v;
    }
    __syncthreads();
    for (int rr = threadIdx.y; rr < 32; rr += 8) {
        float v = tile[threadIdx.x][rr];
        long off = (long)(c0 + rr) * R + r0 + threadIdx.x;
        fp16 h, l; split2h(v, h, l);
        WThi[off] = h;
        if (WTlo) WTlo[off] = l;
    }
}

// ---------------- c19 activation ----------------
__device__ __forceinline__ float c19f(float x, float craw, float rhoraw) {
    float c   = fmaxf(craw, 0.1f);
    float rho = fmaxf(rhoraw, 0.0f);
    float L   = 6.0f * c;
    float s   = x / c;
    float n   = floorf(s);
    float t   = s - n;
    float h   = t * (1.0f - t);
    float sgn = (fmodf(n, 2.0f) == 0.0f) ? 1.0f : -1.0f;
    float interior = c * (sgn * h + rho * h * h);
    return (x >= L) ? (x - L) : ((x <= -L) ? (x + L) : interior);
}

// ---------------- fp16 multi-product GEMM ----------------
// acc = Ahi*Bh + Alo*Bh (+ Ahi*Bl if NPASS==3);  C = s*acc + bias
// B K-major: row n holds K contiguous. Block 128 x (NI*32), 8 warps 2x4,
// warp tile 64 x (NI*8). BK=32. Single K sweep; all products share the stage.
#define BM 128
#define BKK 32

template<int NI, int NPASS, int NSTAGE>
__global__ void __launch_bounds__(256, 1)
gemm_fp16_kernel(const fp16* __restrict__ Ahi, const fp16* __restrict__ Alo,
                 const fp16* __restrict__ Bhi, const fp16* __restrict__ Blo,
                 int M, int Nn, int K,
                 const float* __restrict__ cbk,   // scale = cbk[3]
                 const float* __restrict__ bias, int epi,
                 const float* __restrict__ craw, const float* __restrict__ rho,
                 float* __restrict__ Cf, fp16* __restrict__ Chi, fp16* __restrict__ Clo) {
    constexpr int BN = NI * 32;
    constexpr int A_BYTES = BM * 64;           // one A variant
    constexpr int B_BYTES = BN * 64;           // one B variant
    constexpr int STAGE_BYTES = 2 * A_BYTES + (NPASS == 3 ? 2 : 1) * B_BYTES;
    extern __shared__ char smem[];
    const uint32_t sbase = smem_u32(smem);
    const uint32_t tbase = (sbase + 1023u) & ~1023u;
    const int tid  = threadIdx.x;
    const int wid  = tid >> 5;
    const int lane = tid & 31;
    const int wm = wid & 1;
    const int wn = wid >> 1;

    const int m0 = blockIdx.y * BM;
    const int n0 = blockIdx.x * BN;

    float sc = __ldg(cbk + 3);
    if (sc == 0.0f) sc = 1.0f;

    uint32_t sAh[NSTAGE], sAl[NSTAGE], sBh[NSTAGE], sBl[NSTAGE];
#pragma unroll
    for (int s = 0; s < NSTAGE; s++) {
        uint32_t b = tbase + s * STAGE_BYTES;
        sAh[s] = b;
        sAl[s] = b + A_BYTES;
        sBh[s] = b + 2 * A_BYTES;
        sBl[s] = b + 2 * A_BYTES + B_BYTES;   // valid only if NPASS==3
    }

    const int ITERS = K / BKK;

    float acc[4][NI][4];
#pragma unroll
    for (int i = 0; i < 4; i++)
#pragma unroll
        for (int j = 0; j < NI; j++)
#pragma unroll
            for (int r = 0; r < 4; r++) acc[i][j][r] = 0.0f;

    auto fill = [&](int kc) {
        const int s = kc % NSTAGE;
        const size_t k0 = (size_t)kc * BKK;
#pragma unroll
        for (int i = 0; i < 2; i++) {
            int ch = tid + i * 256;
            int r = ch >> 2, c = ch & 3;
            uint32_t so = SWZ128(r * 64 + c * 16);
            const char* pA = (const char*)(Ahi + (size_t)(m0 + r) * K + k0) + c * 16;
            const char* pL = (const char*)(Alo + (size_t)(m0 + r) * K + k0) + c * 16;
            cp16cp(sAh[s] + so, pA);
            cp16cp(sAl[s] + so, pL);
        }
#pragma unroll
        for (int i = 0; i < NI / 2; i++) {
            int ch = tid + i * 256;
            int r = ch >> 2, c = ch & 3;
            uint32_t so = SWZ128(r * 64 + c * 16);
            const char* pB = (const char*)(Bhi + (size_t)(n0 + r) * K + k0) + c * 16;
            cp16cp(sBh[s] + so, pB);
            if (NPASS == 3) {
                const char* pBl = (const char*)(Blo + (size_t)(n0 + r) * K + k0) + c * 16;
                cp16cp(sBl[s] + so, pBl);
            }
        }
    };

    // prologue
    for (int it = 0; it < NSTAGE - 1; it++) { fill(it); CP_COMMIT(); }

    for (int it = 0; it < ITERS; it++) {
        CP_WAIT(NSTAGE - 2);
        __syncthreads();
        if (it + NSTAGE - 1 < ITERS) fill(it + NSTAGE - 1);
        CP_COMMIT();

        const int s = it % NSTAGE;
#pragma unroll
        for (int kk = 0; kk < 2; kk++) {
            uint32_t afh[4][4], afl[4][4];
#pragma unroll
            for (int mi = 0; mi < 4; mi++) {
                int row = wm * 64 + mi * 16 + (lane & 15);
                int ch  = kk * 2 + (lane >> 4);
                uint32_t so = SWZ128(row * 64 + ch * 16);
                ldsm4(sAh[s] + so, afh[mi][0], afh[mi][1], afh[mi][2], afh[mi][3]);
                ldsm4(sAl[s] + so, afl[mi][0], afl[mi][1], afl[mi][2], afl[mi][3]);
            }
            uint32_t bfh[NI][2], bfl[NI][2];
#pragma unroll
            for (int p = 0; p < NI / 2; p++) {
                int g   = lane >> 3;
                int row = wn * (NI * 8) + (p * 2 + (g >> 1)) * 8 + (lane & 7);
                int ch  = kk * 2 + (g & 1);
                uint32_t so = SWZ128(row * 64 + ch * 16);
                uint32_t r0, r1, r2, r3;
                ldsm4(sBh[s] + so, r0, r1, r2, r3);
                bfh[p * 2][0] = r0;  bfh[p * 2][1] = r1;
                bfh[p * 2 + 1][0] = r2; bfh[p * 2 + 1][1] = r3;
                if (NPASS == 3) {
                    ldsm4(sBl[s] + so, r0, r1, r2, r3);
                    bfl[p * 2][0] = r0;  bfl[p * 2][1] = r1;
                    bfl[p * 2 + 1][0] = r2; bfl[p * 2 + 1][1] = r3;
                }
            }
#pragma unroll
            for (int mi = 0; mi < 4; mi++)
#pragma unroll
                for (int ni = 0; ni < NI; ni++)
                    mma16816(acc[mi][ni], afh[mi], bfh[ni]);
#pragma unroll
            for (int mi = 0; mi < 4; mi++)
#pragma unroll
                for (int ni = 0; ni < NI; ni++)
                    mma16816(acc[mi][ni], afl[mi], bfh[ni]);
            if (NPASS == 3) {
#pragma unroll
                for (int mi = 0; mi < 4; mi++)
#pragma unroll
                    for (int ni = 0; ni < NI; ni++)
                        mma16816(acc[mi][ni], afh[mi], bfl[ni]);
            }
        }
    }

    // ---------------- epilogue: scale + bias (+c19) + outputs ----------------
#pragma unroll
    for (int ni = 0; ni < NI; ni++) {
        const int n = n0 + wn * (NI * 8) + ni * 8 + 2 * (lane & 3);
        const float bv0 = __ldg(bias + n), bv1 = __ldg(bias + n + 1);
        float c0 = 0, c1 = 0, r0 = 0, r1 = 0;
        if (epi) {
            c0 = __ldg(craw + n);  c1 = __ldg(craw + n + 1);
            r0 = __ldg(rho + n);   r1 = __ldg(rho + n + 1);
        }
#pragma unroll
        for (int mi = 0; mi < 4; mi++) {
#pragma unroll
            for (int h = 0; h < 2; h++) {
                const int m = m0 + wm * 64 + mi * 16 + (lane >> 2) + h * 8;
                float v0 = fmaf(sc, acc[mi][ni][2 * h],     bv0);
                float v1 = fmaf(sc, acc[mi][ni][2 * h + 1], bv1);
                if (epi) { v0 = c19f(v0, c0, r0); v1 = c19f(v1, c1, r1); }
                const size_t off = (size_t)m * Nn + n;
                if (Cf) *(float2*)(Cf + off) = make_float2(v0, v1);
                if (Chi) {
                    fp16 h0, l0, h1, l1;
                    split2h(v0, h0, l0); split2h(v1, h1, l1);
                    *(__half2*)(Chi + off) = __halves2half2(h0, h1);
                    *(__half2*)(Clo + off) = __halves2half2(l0, l1);
                }
            }
        }
    }
}

#define SMEM_CFG(NI, NPASS, NSTAGE) \
    (1024 + (NSTAGE) * (2 * BM * 64 + ((NPASS) == 3 ? 2 : 1) * (NI) * 32 * 64))

// ---------------- launch ----------------
extern "C" void kernel_launch(void* const* d_in, const int* in_sizes, int n_in,
                              void* d_out, int out_size) {
    const float* x    = (const float*)d_in[0];
    const float* cb1  = (const float*)d_in[1];
    const float* cb2  = (const float*)d_in[2];
    const float* W1f  = (const float*)d_in[3];
    const float* W2f  = (const float*)d_in[4];
    const float* b1   = (const float*)d_in[5];
    const float* b2   = (const float*)d_in[6];
    const float* db1  = (const float*)d_in[7];
    const float* db2  = (const float*)d_in[8];
    const float* craw = (const float*)d_in[9];
    const float* rraw = (const float*)d_in[10];
    const int*   W1i  = (const int*)d_in[11];
    const int*   W2i  = (const int*)d_in[12];
    const void*  W1m  = d_in[13];
    const void*  W2m  = d_in[14];

    fp16 *xhi, *xlo, *W1hi, *W1Thi, *W1Tlo, *W2hi, *W2Thi;
    fp16 *z1hi, *z1lo, *zhi, *zlo, *thi, *tlo;
    cudaGetSymbolAddress((void**)&xhi,  g_xhi);   cudaGetSymbolAddress((void**)&xlo,  g_xlo);
    cudaGetSymbolAddress((void**)&W1hi, g_W1hi);
    cudaGetSymbolAddress((void**)&W1Thi,g_W1Thi); cudaGetSymbolAddress((void**)&W1Tlo,g_W1Tlo);
    cudaGetSymbolAddress((void**)&W2hi, g_W2hi);
    cudaGetSymbolAddress((void**)&W2Thi,g_W2Thi);
    cudaGetSymbolAddress((void**)&z1hi, g_z1hi);  cudaGetSymbolAddress((void**)&z1lo, g_z1lo);
    cudaGetSymbolAddress((void**)&zhi,  g_zhi);   cudaGetSymbolAddress((void**)&zlo,  g_zlo);
    cudaGetSymbolAddress((void**)&thi,  g_thi);   cudaGetSymbolAddress((void**)&tlo,  g_tlo);

    float* dec = (float*)d_out;
    float* z   = (float*)d_out + (size_t)NBATCH * IN_DIM;

    cudaFuncSetAttribute((const void*)gemm_fp16_kernel<8,3,3>,
                         cudaFuncAttributeMaxDynamicSharedMemorySize, SMEM_CFG(8,3,3));
    cudaFuncSetAttribute((const void*)gemm_fp16_kernel<8,2,4>,
                         cudaFuncAttributeMaxDynamicSharedMemorySize, SMEM_CFG(8,2,4));
    cudaFuncSetAttribute((const void*)gemm_fp16_kernel<4,2,4>,
                         cudaFuncAttributeMaxDynamicSharedMemorySize, SMEM_CFG(4,2,4));

    // 1. mask dtype probe
    detect_mask_kernel<<<1, 256>>>((const unsigned int*)W1m, 4096);

    // 2. split x; dequant (scaled by 1/cb[3]) + split + transpose
    {
        size_t n = (size_t)NBATCH * IN_DIM;
        split_kernel<<<(unsigned)((n + 255) / 256), 256>>>(x, xhi, xlo, n);
    }
    dequant_split_kernel<<<dim3(HDIM / 32, IN_DIM / 32), dim3(32, 8)>>>(
        W1i, W1m, W1f, cb1, W1hi, W1Thi, W1Tlo, IN_DIM, HDIM);
    dequant_split_kernel<<<dim3(OUT_DIM / 32, HDIM / 32), dim3(32, 8)>>>(
        W2i, W2m, W2f, cb2, W2hi, W2Thi, nullptr, HDIM, OUT_DIM);

    // 3. G1: z1 = c19(s1*(x @ Ŵ1) + b1)   3-product   [4096 x 8192]
    gemm_fp16_kernel<8,3,3><<<dim3(HDIM / 256, NBATCH / BM), 256, SMEM_CFG(8,3,3)>>>(
        xhi, xlo, W1Thi, W1Tlo, NBATCH, HDIM, IN_DIM,
        cb1, b1, 1, craw, rraw, nullptr, z1hi, z1lo);

    // 4. G2: z = s2*(z1 @ Ŵ2) + b2        2-product   [4096 x 512]
    gemm_fp16_kernel<4,2,4><<<dim3(OUT_DIM / 128, NBATCH / BM), 256, SMEM_CFG(4,2,4)>>>(
        z1hi, z1lo, W2Thi, nullptr, NBATCH, OUT_DIM, HDIM,
        cb2, b2, 0, nullptr, nullptr, z, zhi, zlo);

    // 5. G3: t = s2*(z @ Ŵ2^T) + db1      2-product   [4096 x 8192]
    gemm_fp16_kernel<8,2,4><<<dim3(HDIM / 256, NBATCH / BM), 256, SMEM_CFG(8,2,4)>>>(
        zhi, zlo, W2hi, nullptr, NBATCH, HDIM, OUT_DIM,
        cb2, db1, 0, nullptr, nullptr, nullptr, thi, tlo);

    // 6. G4: dec = s1*(t @ Ŵ1^T) + db2    2-product   [4096 x 2048]
    gemm_fp16_kernel<8,2,4><<<dim3(IN_DIM / 256, NBATCH / BM), 256, SMEM_CFG(8,2,4)>>>(
        thi, tlo, W1hi, nullptr, NBATCH, IN_DIM, HDIM,
        cb1, db2, 0, nullptr, nullptr, dec, nullptr, nullptr);
}

// round 10
// speedup vs baseline: 1.7273x; 1.2965x over previous
#include <cuda_runtime.h>
#include <cuda_fp16.h>
#include <cstdint>

#define IN_DIM  2048
#define HDIM    8192
#define OUT_DIM 512
#define NBATCH  4096

typedef __half fp16;

// ---------------- scratch (static __device__ per harness rules) ----------------
__device__ __align__(256) fp16 g_xhi [(size_t)NBATCH * IN_DIM];
__device__ __align__(256) fp16 g_xlo [(size_t)NBATCH * IN_DIM];
__device__ __align__(256) fp16 g_W1hi[(size_t)IN_DIM * HDIM];     // Ŵ1 = W1/s1
__device__ __align__(256) fp16 g_W1Thi[(size_t)HDIM * IN_DIM];
__device__ __align__(256) fp16 g_W2hi[(size_t)HDIM * OUT_DIM];    // Ŵ2 = W2/s2
__device__ __align__(256) fp16 g_W2Thi[(size_t)OUT_DIM * HDIM];
__device__ __align__(256) fp16 g_z1hi[(size_t)NBATCH * HDIM];
__device__ __align__(256) fp16 g_z1lo[(size_t)NBATCH * HDIM];
__device__ __align__(256) fp16 g_zhi [(size_t)NBATCH * OUT_DIM];
__device__ __align__(256) fp16 g_zlo [(size_t)NBATCH * OUT_DIM];
__device__ __align__(256) fp16 g_thi [(size_t)NBATCH * HDIM];
__device__ int g_maskmode;

// ---------------- PTX helpers (compute_100-safe) ----------------
__device__ __forceinline__ uint32_t smem_u32(const void* p) {
    uint32_t a;
    asm("{ .reg .u64 t; cvta.to.shared.u64 t, %1; cvt.u32.u64 %0, t; }" : "=r"(a) : "l"(p));
    return a;
}
#define SWZ128(off) ((off) ^ (((off) >> 3) & 0x70))

__device__ __forceinline__ void cp16cp(uint32_t dst, const void* src) {
    asm volatile("cp.async.cg.shared.global [%0], [%1], 16;" :: "r"(dst), "l"(src));
}
#define CP_COMMIT() asm volatile("cp.async.commit_group;" ::: "memory")
#define CP_WAIT(n)  asm volatile("cp.async.wait_group %0;" :: "n"(n) : "memory")

__device__ __forceinline__ void ldsm4(uint32_t a, uint32_t& r0, uint32_t& r1,
                                      uint32_t& r2, uint32_t& r3) {
    asm volatile("ldmatrix.sync.aligned.m8n8.x4.shared.b16 {%0,%1,%2,%3}, [%4];"
                 : "=r"(r0), "=r"(r1), "=r"(r2), "=r"(r3) : "r"(a));
}

__device__ __forceinline__ void mma16816(float* d, const uint32_t* a, const uint32_t* b) {
    asm volatile("mma.sync.aligned.m16n8k16.row.col.f32.f16.f16.f32 "
        "{%0,%1,%2,%3}, {%4,%5,%6,%7}, {%8,%9}, {%0,%1,%2,%3};"
        : "+f"(d[0]), "+f"(d[1]), "+f"(d[2]), "+f"(d[3])
        : "r"(a[0]), "r"(a[1]), "r"(a[2]), "r"(a[3]), "r"(b[0]), "r"(b[1]));
}

// ---------------- mask dtype detection ----------------
__global__ void detect_mask_kernel(const unsigned int* __restrict__ m, int nwords) {
    __shared__ int ok[4];
    if (threadIdx.x < 4) ok[threadIdx.x] = 1;
    __syncthreads();
    for (int i = threadIdx.x; i < nwords; i += blockDim.x) {
        unsigned w = m[i];
        if (!(w == 0u || w == 1u))          atomicAnd(&ok[0], 0);
        if (!(w == 0u || w == 0x3F800000u)) atomicAnd(&ok[1], 0);
        unsigned lo = w & 0xFFFFu, hi = w >> 16;
        if (!((lo == 0u || lo == 0x3F80u) && (hi == 0u || hi == 0x3F80u))) atomicAnd(&ok[2], 0);
        if (!((lo == 0u || lo == 0x3C00u) && (hi == 0u || hi == 0x3C00u))) atomicAnd(&ok[3], 0);
    }
    __syncthreads();
    if (threadIdx.x == 0) {
        int mode = 0;
        if      (ok[0]) mode = 1;
        else if (ok[1]) mode = 2;
        else if (ok[2]) mode = 3;
        else if (ok[3]) mode = 4;
        g_maskmode = mode;
    }
}

__device__ __forceinline__ int read_mask(const void* p, long i, int mode) {
    switch (mode) {
        case 1:  return ((const int*)p)[i] != 0;
        case 2:  return ((const float*)p)[i] != 0.0f;
        case 3:  return ((const unsigned short*)p)[i] != 0;
        case 4:  return ((const unsigned short*)p)[i] != 0;
        default: return ((const unsigned char*)p)[i] != 0;
    }
}

__device__ __forceinline__ void split2h(float v, fp16& h, fp16& l) {
    h = __float2half(v);
    l = __float2half(v - __half2float(h));
}

// ---------------- split x (fp16 hi/lo) ----------------
__global__ void split_kernel(const float* __restrict__ src, fp16* __restrict__ hi,
                             fp16* __restrict__ lo, size_t n) {
    size_t i = (size_t)blockIdx.x * blockDim.x + threadIdx.x;
    if (i < n) {
        fp16 h, l;
        split2h(src[i], h, l);
        hi[i] = h; lo[i] = l;
    }
}

// ---------------- dequant + scale-factor + transpose ----------------
// vhat = (mask ? cb[idx] : wf) / s  with s = cb[3] (exact for codebook entries)
__global__ void dequant_split_kernel(const int* __restrict__ idx, const void* __restrict__ mask,
                                     const float* __restrict__ wf, const float* __restrict__ cb,
                                     fp16* __restrict__ Whi,
                                     fp16* __restrict__ WThi,
                                     int R, int C) {
    __shared__ float tile[32][33];
    const int mode = g_maskmode;
    float s = __ldg(cb + 3);
    if (s == 0.0f) s = 1.0f;
    const int c0 = blockIdx.x * 32;
    const int r0 = blockIdx.y * 32;
    for (int rr = threadIdx.y; rr < 32; rr += 8) {
        long off = (long)(r0 + rr) * C + c0 + threadIdx.x;
        int  m = read_mask(mask, off, mode);
        float v = (m ? cb[idx[off]] : wf[off]) / s;   // exact for codebook
        Whi[off] = __float2half(v);
        tile[rr][threadIdx.x] = v;
    }
    __syncthreads();
    for (int rr = threadIdx.y; rr < 32; rr += 8) {
        float v = tile[threadIdx.x][rr];
        long off = (long)(c0 + rr) * R + r0 + threadIdx.x;
        WThi[off] = __float2half(v);
    }
}

// ---------------- c19 activation ----------------
__device__ __forceinline__ float c19f(float x, float craw, float rhoraw) {
    float c   = fmaxf(craw, 0.1f);
    float rho = fmaxf(rhoraw, 0.0f);
    float L   = 6.0f * c;
    float s   = x / c;
    float n   = floorf(s);
    float t   = s - n;
    float h   = t * (1.0f - t);
    float sgn = (fmodf(n, 2.0f) == 0.0f) ? 1.0f : -1.0f;
    float interior = c * (sgn * h + rho * h * h);
    return (x >= L) ? (x - L) : ((x <= -L) ? (x + L) : interior);
}

// ---------------- fp16 multi-product GEMM ----------------
// NPASS==1: acc = Ahi*Bh
// NPASS==2: acc = Ahi*Bh + Alo*Bh
// C = s*acc + bias;  B K-major (row n holds K). Block 128 x (NI*32),
// 8 warps 2x4, warp tile 64 x (NI*8). BK=32.
#define BM 128
#define BKK 32

template<int NI, int NPASS, int NSTAGE>
__global__ void __launch_bounds__(256, 1)
gemm_fp16_kernel(const fp16* __restrict__ Ahi, const fp16* __restrict__ Alo,
                 const fp16* __restrict__ Bhi,
                 int M, int Nn, int K,
                 const float* __restrict__ cbk,   // scale = cbk[3]
                 const float* __restrict__ bias, int epi,
                 const float* __restrict__ craw, const float* __restrict__ rho,
                 float* __restrict__ Cf, fp16* __restrict__ Chi, fp16* __restrict__ Clo) {
    constexpr int BN = NI * 32;
    constexpr int A_BYTES = BM * 64;
    constexpr int B_BYTES = BN * 64;
    constexpr int NAV = (NPASS >= 2) ? 2 : 1;     // A variants in smem
    constexpr int STAGE_BYTES = NAV * A_BYTES + B_BYTES;
    extern __shared__ char smem[];
    const uint32_t sbase = smem_u32(smem);
    const uint32_t tbase = (sbase + 1023u) & ~1023u;
    const int tid  = threadIdx.x;
    const int wid  = tid >> 5;
    const int lane = tid & 31;
    const int wm = wid & 1;
    const int wn = wid >> 1;

    const int m0 = blockIdx.y * BM;
    const int n0 = blockIdx.x * BN;

    float sc = __ldg(cbk + 3);
    if (sc == 0.0f) sc = 1.0f;

    uint32_t sAh[NSTAGE], sAl[NSTAGE], sBh[NSTAGE];
#pragma unroll
    for (int s = 0; s < NSTAGE; s++) {
        uint32_t b = tbase + s * STAGE_BYTES;
        sAh[s] = b;
        sAl[s] = b + A_BYTES;                     // valid only if NPASS>=2
        sBh[s] = b + NAV * A_BYTES;
    }

    const int ITERS = K / BKK;

    float acc[4][NI][4];
#pragma unroll
    for (int i = 0; i < 4; i++)
#pragma unroll
        for (int j = 0; j < NI; j++)
#pragma unroll
            for (int r = 0; r < 4; r++) acc[i][j][r] = 0.0f;

    auto fill = [&](int kc) {
        const int s = kc % NSTAGE;
        const size_t k0 = (size_t)kc * BKK;
#pragma unroll
        for (int i = 0; i < 2; i++) {
            int ch = tid + i * 256;
            int r = ch >> 2, c = ch & 3;
            uint32_t so = SWZ128(r * 64 + c * 16);
            const char* pA = (const char*)(Ahi + (size_t)(m0 + r) * K + k0) + c * 16;
            cp16cp(sAh[s] + so, pA);
            if (NPASS >= 2) {
                const char* pL = (const char*)(Alo + (size_t)(m0 + r) * K + k0) + c * 16;
                cp16cp(sAl[s] + so, pL);
            }
        }
#pragma unroll
        for (int i = 0; i < NI / 2; i++) {
            int ch = tid + i * 256;
            int r = ch >> 2, c = ch & 3;
            uint32_t so = SWZ128(r * 64 + c * 16);
            const char* pB = (const char*)(Bhi + (size_t)(n0 + r) * K + k0) + c * 16;
            cp16cp(sBh[s] + so, pB);
        }
    };

    // prologue
    for (int it = 0; it < NSTAGE - 1; it++) { fill(it); CP_COMMIT(); }

    for (int it = 0; it < ITERS; it++) {
        CP_WAIT(NSTAGE - 2);
        __syncthreads();
        if (it + NSTAGE - 1 < ITERS) fill(it + NSTAGE - 1);
        CP_COMMIT();

        const int s = it % NSTAGE;
#pragma unroll
        for (int kk = 0; kk < 2; kk++) {
            uint32_t afh[4][4], afl[4][4];
#pragma unroll
            for (int mi = 0; mi < 4; mi++) {
                int row = wm * 64 + mi * 16 + (lane & 15);
                int ch  = kk * 2 + (lane >> 4);
                uint32_t so = SWZ128(row * 64 + ch * 16);
                ldsm4(sAh[s] + so, afh[mi][0], afh[mi][1], afh[mi][2], afh[mi][3]);
                if (NPASS >= 2)
                    ldsm4(sAl[s] + so, afl[mi][0], afl[mi][1], afl[mi][2], afl[mi][3]);
            }
            uint32_t bfh[NI][2];
#pragma unroll
            for (int p = 0; p < NI / 2; p++) {
                int g   = lane >> 3;
                int row = wn * (NI * 8) + (p * 2 + (g >> 1)) * 8 + (lane & 7);
                int ch  = kk * 2 + (g & 1);
                uint32_t so = SWZ128(row * 64 + ch * 16);
                uint32_t r0, r1, r2, r3;
                ldsm4(sBh[s] + so, r0, r1, r2, r3);
                bfh[p * 2][0] = r0;  bfh[p * 2][1] = r1;
                bfh[p * 2 + 1][0] = r2; bfh[p * 2 + 1][1] = r3;
            }
#pragma unroll
            for (int mi = 0; mi < 4; mi++)
#pragma unroll
                for (int ni = 0; ni < NI; ni++)
                    mma16816(acc[mi][ni], afh[mi], bfh[ni]);
            if (NPASS >= 2) {
#pragma unroll
                for (int mi = 0; mi < 4; mi++)
#pragma unroll
                    for (int ni = 0; ni < NI; ni++)
                        mma16816(acc[mi][ni], afl[mi], bfh[ni]);
            }
        }
    }

    // ---------------- epilogue: scale + bias (+c19) + outputs ----------------
#pragma unroll
    for (int ni = 0; ni < NI; ni++) {
        const int n = n0 + wn * (NI * 8) + ni * 8 + 2 * (lane & 3);
        const float bv0 = __ldg(bias + n), bv1 = __ldg(bias + n + 1);
        float c0 = 0, c1 = 0, r0 = 0, r1 = 0;
        if (epi) {
            c0 = __ldg(craw + n);  c1 = __ldg(craw + n + 1);
            r0 = __ldg(rho + n);   r1 = __ldg(rho + n + 1);
        }
#pragma unroll
        for (int mi = 0; mi < 4; mi++) {
#pragma unroll
            for (int h = 0; h < 2; h++) {
                const int m = m0 + wm * 64 + mi * 16 + (lane >> 2) + h * 8;
                float v0 = fmaf(sc, acc[mi][ni][2 * h],     bv0);
                float v1 = fmaf(sc, acc[mi][ni][2 * h + 1], bv1);
                if (epi) { v0 = c19f(v0, c0, r0); v1 = c19f(v1, c1, r1); }
                const size_t off = (size_t)m * Nn + n;
                if (Cf) *(float2*)(Cf + off) = make_float2(v0, v1);
                if (Chi) {
                    fp16 h0, l0, h1, l1;
                    split2h(v0, h0, l0); split2h(v1, h1, l1);
                    *(__half2*)(Chi + off) = __halves2half2(h0, h1);
                    if (Clo) *(__half2*)(Clo + off) = __halves2half2(l0, l1);
                }
            }
        }
    }
}

#define SMEM_CFG(NI, NPASS, NSTAGE) \
    (1024 + (NSTAGE) * ((((NPASS) >= 2) ? 2 : 1) * BM * 64 + (NI) * 32 * 64))

// ---------------- launch ----------------
extern "C" void kernel_launch(void* const* d_in, const int* in_sizes, int n_in,
                              void* d_out, int out_size) {
    const float* x    = (const float*)d_in[0];
    const float* cb1  = (const float*)d_in[1];
    const float* cb2  = (const float*)d_in[2];
    const float* W1f  = (const float*)d_in[3];
    const float* W2f  = (const float*)d_in[4];
    const float* b1   = (const float*)d_in[5];
    const float* b2   = (const float*)d_in[6];
    const float* db1  = (const float*)d_in[7];
    const float* db2  = (const float*)d_in[8];
    const float* craw = (const float*)d_in[9];
    const float* rraw = (const float*)d_in[10];
    const int*   W1i  = (const int*)d_in[11];
    const int*   W2i  = (const int*)d_in[12];
    const void*  W1m  = d_in[13];
    const void*  W2m  = d_in[14];

    fp16 *xhi, *xlo, *W1hi, *W1Thi, *W2hi, *W2Thi;
    fp16 *z1hi, *z1lo, *zhi, *zlo, *thi;
    cudaGetSymbolAddress((void**)&xhi,  g_xhi);   cudaGetSymbolAddress((void**)&xlo,  g_xlo);
    cudaGetSymbolAddress((void**)&W1hi, g_W1hi);
    cudaGetSymbolAddress((void**)&W1Thi,g_W1Thi);
    cudaGetSymbolAddress((void**)&W2hi, g_W2hi);
    cudaGetSymbolAddress((void**)&W2Thi,g_W2Thi);
    cudaGetSymbolAddress((void**)&z1hi, g_z1hi);  cudaGetSymbolAddress((void**)&z1lo, g_z1lo);
    cudaGetSymbolAddress((void**)&zhi,  g_zhi);   cudaGetSymbolAddress((void**)&zlo,  g_zlo);
    cudaGetSymbolAddress((void**)&thi,  g_thi);

    float* dec = (float*)d_out;
    float* z   = (float*)d_out + (size_t)NBATCH * IN_DIM;

    cudaFuncSetAttribute((const void*)gemm_fp16_kernel<8,2,4>,
                         cudaFuncAttributeMaxDynamicSharedMemorySize, SMEM_CFG(8,2,4));
    cudaFuncSetAttribute((const void*)gemm_fp16_kernel<4,2,4>,
                         cudaFuncAttributeMaxDynamicSharedMemorySize, SMEM_CFG(4,2,4));
    cudaFuncSetAttribute((const void*)gemm_fp16_kernel<8,1,5>,
                         cudaFuncAttributeMaxDynamicSharedMemorySize, SMEM_CFG(8,1,5));

    // 1. mask dtype probe
    detect_mask_kernel<<<1, 256>>>((const unsigned int*)W1m, 4096);

    // 2. split x; dequant (scaled by 1/cb[3]) + transpose
    {
        size_t n = (size_t)NBATCH * IN_DIM;
        split_kernel<<<(unsigned)((n + 255) / 256), 256>>>(x, xhi, xlo, n);
    }
    dequant_split_kernel<<<dim3(HDIM / 32, IN_DIM / 32), dim3(32, 8)>>>(
        W1i, W1m, W1f, cb1, W1hi, W1Thi, IN_DIM, HDIM);
    dequant_split_kernel<<<dim3(OUT_DIM / 32, HDIM / 32), dim3(32, 8)>>>(
        W2i, W2m, W2f, cb2, W2hi, W2Thi, HDIM, OUT_DIM);

    // 3. G1: z1 = c19(s1*(x @ Ŵ1) + b1)   2-product   [4096 x 8192]
    gemm_fp16_kernel<8,2,4><<<dim3(HDIM / 256, NBATCH / BM), 256, SMEM_CFG(8,2,4)>>>(
        xhi, xlo, W1Thi, NBATCH, HDIM, IN_DIM,
        cb1, b1, 1, craw, rraw, nullptr, z1hi, z1lo);

    // 4. G2: z = s2*(z1 @ Ŵ2) + b2        2-product   [4096 x 512]
    gemm_fp16_kernel<4,2,4><<<dim3(OUT_DIM / 128, NBATCH / BM), 256, SMEM_CFG(4,2,4)>>>(
        z1hi, z1lo, W2Thi, NBATCH, OUT_DIM, HDIM,
        cb2, b2, 0, nullptr, nullptr, z, zhi, zlo);

    // 5. G3: t = s2*(z @ Ŵ2^T) + db1      2-product   [4096 x 8192]
    gemm_fp16_kernel<8,2,4><<<dim3(HDIM / 256, NBATCH / BM), 256, SMEM_CFG(8,2,4)>>>(
        zhi, zlo, W2hi, NBATCH, HDIM, OUT_DIM,
        cb2, db1, 0, nullptr, nullptr, nullptr, thi, nullptr);

    // 6. G4: dec = s1*(t @ Ŵ1^T) + db2    1-product   [4096 x 2048]
    gemm_fp16_kernel<8,1,5><<<dim3(IN_DIM / 256, NBATCH / BM), 256, SMEM_CFG(8,1,5)>>>(
        thi, nullptr, W1hi, NBATCH, IN_DIM, HDIM,
        cb1, db2, 0, nullptr, nullptr, dec, nullptr, nullptr);
}

// round 11
// speedup vs baseline: 2.1604x; 1.2507x over previous
#include <cuda_runtime.h>
#include <cuda_fp16.h>
#include <cstdint>

#define IN_DIM  2048
#define HDIM    8192
#define OUT_DIM 512
#define NBATCH  4096

typedef __half fp16;

// ---------------- scratch (static __device__ per harness rules) ----------------
__device__ __align__(256) fp16 g_xhi [(size_t)NBATCH * IN_DIM];
__device__ __align__(256) fp16 g_xlo [(size_t)NBATCH * IN_DIM];
__device__ __align__(256) fp16 g_W1hi[(size_t)IN_DIM * HDIM];     // Ŵ1 = W1/s1
__device__ __align__(256) fp16 g_W1lo[(size_t)IN_DIM * HDIM];
__device__ __align__(256) fp16 g_W1Thi[(size_t)HDIM * IN_DIM];
__device__ __align__(256) fp16 g_W2Thi[(size_t)OUT_DIM * HDIM];   // Ŵ2ᵀ = (W2/s2)ᵀ
__device__ __align__(256) fp16 g_z1hi[(size_t)NBATCH * HDIM];
__device__ __align__(256) fp16 g_z1lo[(size_t)NBATCH * HDIM];
__device__ __align__(256) fp16 g_zhi [(size_t)NBATCH * OUT_DIM];
__device__ __align__(256) fp16 g_zlo [(size_t)NBATCH * OUT_DIM];
__device__ __align__(256) float g_Mpart[(size_t)4 * IN_DIM * OUT_DIM];  // K-split partials
__device__ __align__(256) fp16 g_Mhi [(size_t)IN_DIM * OUT_DIM];  // M̂ = Ŵ1@Ŵ2
__device__ __align__(256) fp16 g_Mlo [(size_t)IN_DIM * OUT_DIM];
__device__ __align__(256) float g_dvec[IN_DIM];                   // db1@W1ᵀ + db2
__device__ int g_maskmode;

// ---------------- PTX helpers (compute_100-safe) ----------------
__device__ __forceinline__ uint32_t smem_u32(const void* p) {
    uint32_t a;
    asm("{ .reg .u64 t; cvta.to.shared.u64 t, %1; cvt.u32.u64 %0, t; }" : "=r"(a) : "l"(p));
    return a;
}
#define SWZ128(off) ((off) ^ (((off) >> 3) & 0x70))

__device__ __forceinline__ void cp16cp(uint32_t dst, const void* src) {
    asm volatile("cp.async.cg.shared.global [%0], [%1], 16;" :: "r"(dst), "l"(src));
}
#define CP_COMMIT() asm volatile("cp.async.commit_group;" ::: "memory")
#define CP_WAIT(n)  asm volatile("cp.async.wait_group %0;" :: "n"(n) : "memory")

__device__ __forceinline__ void ldsm4(uint32_t a, uint32_t& r0, uint32_t& r1,
                                      uint32_t& r2, uint32_t& r3) {
    asm volatile("ldmatrix.sync.aligned.m8n8.x4.shared.b16 {%0,%1,%2,%3}, [%4];"
                 : "=r"(r0), "=r"(r1), "=r"(r2), "=r"(r3) : "r"(a));
}

__device__ __forceinline__ void mma16816(float* d, const uint32_t* a, const uint32_t* b) {
    asm volatile("mma.sync.aligned.m16n8k16.row.col.f32.f16.f16.f32 "
        "{%0,%1,%2,%3}, {%4,%5,%6,%7}, {%8,%9}, {%0,%1,%2,%3};"
        : "+f"(d[0]), "+f"(d[1]), "+f"(d[2]), "+f"(d[3])
        : "r"(a[0]), "r"(a[1]), "r"(a[2]), "r"(a[3]), "r"(b[0]), "r"(b[1]));
}

// ---------------- mask dtype detection ----------------
__global__ void detect_mask_kernel(const unsigned int* __restrict__ m, int nwords) {
    __shared__ int ok[4];
    if (threadIdx.x < 4) ok[threadIdx.x] = 1;
    __syncthreads();
    for (int i = threadIdx.x; i < nwords; i += blockDim.x) {
        unsigned w = m[i];
        if (!(w == 0u || w == 1u))          atomicAnd(&ok[0], 0);
        if (!(w == 0u || w == 0x3F800000u)) atomicAnd(&ok[1], 0);
        unsigned lo = w & 0xFFFFu, hi = w >> 16;
        if (!((lo == 0u || lo == 0x3F80u) && (hi == 0u || hi == 0x3F80u))) atomicAnd(&ok[2], 0);
        if (!((lo == 0u || lo == 0x3C00u) && (hi == 0u || hi == 0x3C00u))) atomicAnd(&ok[3], 0);
    }
    __syncthreads();
    if (threadIdx.x == 0) {
        int mode = 0;
        if      (ok[0]) mode = 1;
        else if (ok[1]) mode = 2;
        else if (ok[2]) mode = 3;
        else if (ok[3]) mode = 4;
        g_maskmode = mode;
    }
}

__device__ __forceinline__ int read_mask(const void* p, long i, int mode) {
    switch (mode) {
        case 1:  return ((const int*)p)[i] != 0;
        case 2:  return ((const float*)p)[i] != 0.0f;
        case 3:  return ((const unsigned short*)p)[i] != 0;
        case 4:  return ((const unsigned short*)p)[i] != 0;
        default: return ((const unsigned char*)p)[i] != 0;
    }
}

__device__ __forceinline__ void split2h(float v, fp16& h, fp16& l) {
    h = __float2half(v);
    l = __float2half(v - __half2float(h));
}

// ---------------- split x ----------------
__global__ void split_kernel(const float* __restrict__ src, fp16* __restrict__ hi,
                             fp16* __restrict__ lo, size_t n) {
    size_t i = (size_t)blockIdx.x * blockDim.x + threadIdx.x;
    if (i < n) {
        fp16 h, l;
        split2h(src[i], h, l);
        hi[i] = h; lo[i] = l;
    }
}

// ---------------- dequant + scale-factor + split + transpose ----------------
// vhat = (mask ? cb[idx] : wf) / s, s = cb[3] (exact for codebook entries).
// All outputs nullable.
__global__ void dequant_split_kernel(const int* __restrict__ idx, const void* __restrict__ mask,
                                     const float* __restrict__ wf, const float* __restrict__ cb,
                                     fp16* __restrict__ Whi, fp16* __restrict__ Wlo,
                                     fp16* __restrict__ WThi,
                                     int R, int C) {
    __shared__ float tile[32][33];
    const int mode = g_maskmode;
    float s = __ldg(cb + 3);
    if (s == 0.0f) s = 1.0f;
    const int c0 = blockIdx.x * 32;
    const int r0 = blockIdx.y * 32;
    for (int rr = threadIdx.y; rr < 32; rr += 8) {
        long off = (long)(r0 + rr) * C + c0 + threadIdx.x;
        int  m = read_mask(mask, off, mode);
        float v = (m ? cb[idx[off]] : wf[off]) / s;   // exact for codebook
        fp16 h, l; split2h(v, h, l);
        if (Whi) Whi[off] = h;
        if (Wlo) Wlo[off] = l;
        tile[rr][threadIdx.x] = v;
    }
    __syncthreads();
    if (WThi) {
        for (int rr = threadIdx.y; rr < 32; rr += 8) {
            float v = tile[threadIdx.x][rr];
            long off = (long)(c0 + rr) * R + r0 + threadIdx.x;
            WThi[off] = __float2half(v);
        }
    }
}

// ---------------- K-split reduce + fp16 split for M ----------------
__global__ void reduce_split_kernel(const float* __restrict__ part,
                                    fp16* __restrict__ Mhi, fp16* __restrict__ Mlo,
                                    size_t n) {
    size_t i = (size_t)blockIdx.x * blockDim.x + threadIdx.x;
    if (i < n) {
        float v = part[i] + part[i + n] + part[i + 2 * n] + part[i + 3 * n];
        fp16 h, l; split2h(v, h, l);
        Mhi[i] = h; Mlo[i] = l;
    }
}

// ---------------- dvec = s1*(db1 @ Ŵ1ᵀ) + db2  (fp32, one block per row) ----
__global__ void dvec_kernel(const fp16* __restrict__ W1hi, const fp16* __restrict__ W1lo,
                            const float* __restrict__ db1, const float* __restrict__ db2,
                            const float* __restrict__ cb1, float* __restrict__ dvec) {
    __shared__ float red[256];
    const int j = blockIdx.x;
    float s = __ldg(cb1 + 3);
    if (s == 0.0f) s = 1.0f;
    float sum = 0.0f;
    const size_t base = (size_t)j * HDIM;
    for (int h = threadIdx.x; h < HDIM; h += 256)
        sum += (__half2float(W1hi[base + h]) + __half2float(W1lo[base + h])) * __ldg(db1 + h);
    red[threadIdx.x] = sum;
    __syncthreads();
    for (int st = 128; st > 0; st >>= 1) {
        if (threadIdx.x < st) red[threadIdx.x] += red[threadIdx.x + st];
        __syncthreads();
    }
    if (threadIdx.x == 0) dvec[j] = fmaf(s, red[0], __ldg(db2 + j));
}

// ---------------- c19 activation ----------------
__device__ __forceinline__ float c19f(float x, float craw, float rhoraw) {
    float c   = fmaxf(craw, 0.1f);
    float rho = fmaxf(rhoraw, 0.0f);
    float L   = 6.0f * c;
    float s   = x / c;
    float n   = floorf(s);
    float t   = s - n;
    float h   = t * (1.0f - t);
    float sgn = (fmodf(n, 2.0f) == 0.0f) ? 1.0f : -1.0f;
    float interior = c * (sgn * h + rho * h * h);
    return (x >= L) ? (x - L) : ((x <= -L) ? (x + L) : interior);
}

// ---------------- fp16 multi-product GEMM ----------------
// acc = Ahi*Bhi (+ Alo*Bhi if PA==2) (+ Ahi*Blo if PB==2)
// C = sa*sb*acc + bias (nullable). B K-major. Block 128 x (NI*32), 8 warps 2x4.
// gridDim.z = K-splits: CTA z handles K window [z*Klen, (z+1)*Klen), writes
// Cf + z*M*Nn (partials). ldk = full row stride of A and B.
#define BM 128
#define BKK 32

template<int NI, int PA, int PB, int NSTAGE>
__global__ void __launch_bounds__(256, 1)
gemm_fp16_kernel(const fp16* __restrict__ Ahi, const fp16* __restrict__ Alo,
                 const fp16* __restrict__ Bhi, const fp16* __restrict__ Blo,
                 int M, int Nn, int Klen, int ldk,
                 const float* __restrict__ cba, const float* __restrict__ cbb,
                 const float* __restrict__ bias, int epi,
                 const float* __restrict__ craw, const float* __restrict__ rho,
                 float* __restrict__ Cf, fp16* __restrict__ Chi, fp16* __restrict__ Clo) {
    constexpr int BN = NI * 32;
    constexpr int A_BYTES = BM * 64;
    constexpr int B_BYTES = BN * 64;
    constexpr int STAGE_BYTES = PA * A_BYTES + PB * B_BYTES;
    extern __shared__ char smem[];
    const uint32_t sbase = smem_u32(smem);
    const uint32_t tbase = (sbase + 1023u) & ~1023u;
    const int tid  = threadIdx.x;
    const int wid  = tid >> 5;
    const int lane = tid & 31;
    const int wm = wid & 1;
    const int wn = wid >> 1;

    const int m0 = blockIdx.y * BM;
    const int n0 = blockIdx.x * BN;
    const size_t kbase = (size_t)blockIdx.z * Klen;

    float sa = cba ? __ldg(cba + 3) : 1.0f;  if (sa == 0.0f) sa = 1.0f;
    float sb = cbb ? __ldg(cbb + 3) : 1.0f;  if (sb == 0.0f) sb = 1.0f;
    const float sc = sa * sb;

    uint32_t sAh[NSTAGE], sAl[NSTAGE], sBh[NSTAGE], sBl[NSTAGE];
#pragma unroll
    for (int s = 0; s < NSTAGE; s++) {
        uint32_t b = tbase + s * STAGE_BYTES;
        sAh[s] = b;
        sAl[s] = b + A_BYTES;                         // valid if PA==2
        sBh[s] = b + PA * A_BYTES;
        sBl[s] = b + PA * A_BYTES + B_BYTES;          // valid if PB==2
    }

    const int ITERS = Klen / BKK;

    float acc[4][NI][4];
#pragma unroll
    for (int i = 0; i < 4; i++)
#pragma unroll
        for (int j = 0; j < NI; j++)
#pragma unroll
            for (int r = 0; r < 4; r++) acc[i][j][r] = 0.0f;

    auto fill = [&](int kc) {
        const int s = kc % NSTAGE;
        const size_t k0 = kbase + (size_t)kc * BKK;
#pragma unroll
        for (int i = 0; i < 2; i++) {
            int ch = tid + i * 256;
            int r = ch >> 2, c = ch & 3;
            uint32_t so = SWZ128(r * 64 + c * 16);
            const char* pA = (const char*)(Ahi + (size_t)(m0 + r) * ldk + k0) + c * 16;
            cp16cp(sAh[s] + so, pA);
            if (PA == 2) {
                const char* pL = (const char*)(Alo + (size_t)(m0 + r) * ldk + k0) + c * 16;
                cp16cp(sAl[s] + so, pL);
            }
        }
#pragma unroll
        for (int i = 0; i < NI / 2; i++) {
            int ch = tid + i * 256;
            int r = ch >> 2, c = ch & 3;
            uint32_t so = SWZ128(r * 64 + c * 16);
            const char* pB = (const char*)(Bhi + (size_t)(n0 + r) * ldk + k0) + c * 16;
            cp16cp(sBh[s] + so, pB);
            if (PB == 2) {
                const char* pBl = (const char*)(Blo + (size_t)(n0 + r) * ldk + k0) + c * 16;
                cp16cp(sBl[s] + so, pBl);
            }
        }
    };

    // prologue
    for (int it = 0; it < NSTAGE - 1; it++) { fill(it); CP_COMMIT(); }

    for (int it = 0; it < ITERS; it++) {
        CP_WAIT(NSTAGE - 2);
        __syncthreads();
        if (it + NSTAGE - 1 < ITERS) fill(it + NSTAGE - 1);
        CP_COMMIT();

        const int s = it % NSTAGE;
#pragma unroll
        for (int kk = 0; kk < 2; kk++) {
            uint32_t afh[4][4], afl[4][4];
#pragma unroll
            for (int mi = 0; mi < 4; mi++) {
                int row = wm * 64 + mi * 16 + (lane & 15);
                int ch  = kk * 2 + (lane >> 4);
                uint32_t so = SWZ128(row * 64 + ch * 16);
                ldsm4(sAh[s] + so, afh[mi][0], afh[mi][1], afh[mi][2], afh[mi][3]);
                if (PA == 2)
                    ldsm4(sAl[s] + so, afl[mi][0], afl[mi][1], afl[mi][2], afl[mi][3]);
            }
            uint32_t bfh[NI][2], bfl[NI][2];
#pragma unroll
            for (int p = 0; p < NI / 2; p++) {
                int g   = lane >> 3;
                int row = wn * (NI * 8) + (p * 2 + (g >> 1)) * 8 + (lane & 7);
                int ch  = kk * 2 + (g & 1);
                uint32_t so = SWZ128(row * 64 + ch * 16);
                uint32_t r0, r1, r2, r3;
                ldsm4(sBh[s] + so, r0, r1, r2, r3);
                bfh[p * 2][0] = r0;  bfh[p * 2][1] = r1;
                bfh[p * 2 + 1][0] = r2; bfh[p * 2 + 1][1] = r3;
                if (PB == 2) {
                    ldsm4(sBl[s] + so, r0, r1, r2, r3);
                    bfl[p * 2][0] = r0;  bfl[p * 2][1] = r1;
                    bfl[p * 2 + 1][0] = r2; bfl[p * 2 + 1][1] = r3;
                }
            }
#pragma unroll
            for (int mi = 0; mi < 4; mi++)
#pragma unroll
                for (int ni = 0; ni < NI; ni++)
                    mma16816(acc[mi][ni], afh[mi], bfh[ni]);
            if (PA == 2) {
#pragma unroll
                for (int mi = 0; mi < 4; mi++)
#pragma unroll
                    for (int ni = 0; ni < NI; ni++)
                        mma16816(acc[mi][ni], afl[mi], bfh[ni]);
            }
            if (PB == 2) {
#pragma unroll
                for (int mi = 0; mi < 4; mi++)
#pragma unroll
                    for (int ni = 0; ni < NI; ni++)
                        mma16816(acc[mi][ni], afh[mi], bfl[ni]);
            }
        }
    }

    // ---------------- epilogue: scale + bias (+c19) + outputs ----------------
    float* CfZ = Cf ? Cf + (size_t)blockIdx.z * M * Nn : nullptr;
#pragma unroll
    for (int ni = 0; ni < NI; ni++) {
        const int n = n0 + wn * (NI * 8) + ni * 8 + 2 * (lane & 3);
        const float bv0 = bias ? __ldg(bias + n)     : 0.0f;
        const float bv1 = bias ? __ldg(bias + n + 1) : 0.0f;
        float c0 = 0, c1 = 0, r0 = 0, r1 = 0;
        if (epi) {
            c0 = __ldg(craw + n);  c1 = __ldg(craw + n + 1);
            r0 = __ldg(rho + n);   r1 = __ldg(rho + n + 1);
        }
#pragma unroll
        for (int mi = 0; mi < 4; mi++) {
#pragma unroll
            for (int h = 0; h < 2; h++) {
                const int m = m0 + wm * 64 + mi * 16 + (lane >> 2) + h * 8;
                float v0 = fmaf(sc, acc[mi][ni][2 * h],     bv0);
                float v1 = fmaf(sc, acc[mi][ni][2 * h + 1], bv1);
                if (epi) { v0 = c19f(v0, c0, r0); v1 = c19f(v1, c1, r1); }
                const size_t off = (size_t)m * Nn + n;
                if (CfZ) *(float2*)(CfZ + off) = make_float2(v0, v1);
                if (Chi) {
                    fp16 h0, l0, h1, l1;
                    split2h(v0, h0, l0); split2h(v1, h1, l1);
                    *(__half2*)(Chi + off) = __halves2half2(h0, h1);
                    if (Clo) *(__half2*)(Clo + off) = __halves2half2(l0, l1);
                }
            }
        }
    }
}

#define SMEM_CFG(NI, PA, PB, NSTAGE) \
    (1024 + (NSTAGE) * ((PA) * BM * 64 + (PB) * (NI) * 32 * 64))

// ---------------- launch ----------------
extern "C" void kernel_launch(void* const* d_in, const int* in_sizes, int n_in,
                              void* d_out, int out_size) {
    const float* x    = (const float*)d_in[0];
    const float* cb1  = (const float*)d_in[1];
    const float* cb2  = (const float*)d_in[2];
    const float* W1f  = (const float*)d_in[3];
    const float* W2f  = (const float*)d_in[4];
    const float* b1   = (const float*)d_in[5];
    const float* b2   = (const float*)d_in[6];
    const float* db1  = (const float*)d_in[7];
    const float* db2  = (const float*)d_in[8];
    const float* craw = (const float*)d_in[9];
    const float* rraw = (const float*)d_in[10];
    const int*   W1i  = (const int*)d_in[11];
    const int*   W2i  = (const int*)d_in[12];
    const void*  W1m  = d_in[13];
    const void*  W2m  = d_in[14];

    fp16 *xhi, *xlo, *W1hi, *W1lo, *W1Thi, *W2Thi;
    fp16 *z1hi, *z1lo, *zhi, *zlo, *Mhi, *Mlo;
    float *Mpart, *dvec;
    cudaGetSymbolAddress((void**)&xhi,  g_xhi);   cudaGetSymbolAddress((void**)&xlo,  g_xlo);
    cudaGetSymbolAddress((void**)&W1hi, g_W1hi);  cudaGetSymbolAddress((void**)&W1lo, g_W1lo);
    cudaGetSymbolAddress((void**)&W1Thi,g_W1Thi);
    cudaGetSymbolAddress((void**)&W2Thi,g_W2Thi);
    cudaGetSymbolAddress((void**)&z1hi, g_z1hi);  cudaGetSymbolAddress((void**)&z1lo, g_z1lo);
    cudaGetSymbolAddress((void**)&zhi,  g_zhi);   cudaGetSymbolAddress((void**)&zlo,  g_zlo);
    cudaGetSymbolAddress((void**)&Mpart,g_Mpart);
    cudaGetSymbolAddress((void**)&Mhi,  g_Mhi);   cudaGetSymbolAddress((void**)&Mlo,  g_Mlo);
    cudaGetSymbolAddress((void**)&dvec, g_dvec);

    float* dec = (float*)d_out;
    float* z   = (float*)d_out + (size_t)NBATCH * IN_DIM;

    cudaFuncSetAttribute((const void*)gemm_fp16_kernel<8,2,1,4>,
                         cudaFuncAttributeMaxDynamicSharedMemorySize, SMEM_CFG(8,2,1,4));
    cudaFuncSetAttribute((const void*)gemm_fp16_kernel<4,2,1,4>,
                         cudaFuncAttributeMaxDynamicSharedMemorySize, SMEM_CFG(4,2,1,4));
    cudaFuncSetAttribute((const void*)gemm_fp16_kernel<4,2,2,4>,
                         cudaFuncAttributeMaxDynamicSharedMemorySize, SMEM_CFG(4,2,2,4));

    // 1. mask dtype probe
    detect_mask_kernel<<<1, 256>>>((const unsigned int*)W1m, 4096);

    // 2. split x; dequant (scaled by 1/cb[3])
    {
        size_t n = (size_t)NBATCH * IN_DIM;
        split_kernel<<<(unsigned)((n + 255) / 256), 256>>>(x, xhi, xlo, n);
    }
    dequant_split_kernel<<<dim3(HDIM / 32, IN_DIM / 32), dim3(32, 8)>>>(
        W1i, W1m, W1f, cb1, W1hi, W1lo, W1Thi, IN_DIM, HDIM);
    dequant_split_kernel<<<dim3(OUT_DIM / 32, HDIM / 32), dim3(32, 8)>>>(
        W2i, W2m, W2f, cb2, nullptr, nullptr, W2Thi, HDIM, OUT_DIM);

    // 3. GM: M̂ = Ŵ1 @ Ŵ2 (2-product, K-split 4)   [2048 x 512], K=8192
    gemm_fp16_kernel<4,2,1,4><<<dim3(OUT_DIM / 128, IN_DIM / BM, 4), 256, SMEM_CFG(4,2,1,4)>>>(
        W1hi, W1lo, W2Thi, nullptr, IN_DIM, OUT_DIM, HDIM / 4, HDIM,
        nullptr, nullptr, nullptr, 0, nullptr, nullptr, Mpart, nullptr, nullptr);
    {
        size_t n = (size_t)IN_DIM * OUT_DIM;
        reduce_split_kernel<<<(unsigned)((n + 255) / 256), 256>>>(Mpart, Mhi, Mlo, n);
    }

    // 4. dvec = s1*(db1 @ Ŵ1ᵀ) + db2
    dvec_kernel<<<IN_DIM, 256>>>(W1hi, W1lo, db1, db2, cb1, dvec);

    // 5. G1: z1 = c19(s1*(x @ Ŵ1) + b1)   2-product   [4096 x 8192], K=2048
    gemm_fp16_kernel<8,2,1,4><<<dim3(HDIM / 256, NBATCH / BM), 256, SMEM_CFG(8,2,1,4)>>>(
        xhi, xlo, W1Thi, nullptr, NBATCH, HDIM, IN_DIM, IN_DIM,
        cb1, nullptr, b1, 1, craw, rraw, nullptr, z1hi, z1lo);

    // 6. G2: z = s2*(z1 @ Ŵ2) + b2        2-product   [4096 x 512], K=8192
    gemm_fp16_kernel<4,2,1,4><<<dim3(OUT_DIM / 128, NBATCH / BM), 256, SMEM_CFG(4,2,1,4)>>>(
        z1hi, z1lo, W2Thi, nullptr, NBATCH, OUT_DIM, HDIM, HDIM,
        cb2, nullptr, b2, 0, nullptr, nullptr, z, zhi, zlo);

    // 7. G5: dec = s1*s2*(z @ M̂ᵀ) + dvec  3-product   [4096 x 2048], K=512
    gemm_fp16_kernel<4,2,2,4><<<dim3(IN_DIM / 128, NBATCH / BM), 256, SMEM_CFG(4,2,2,4)>>>(
        zhi, zlo, Mhi, Mlo, NBATCH, IN_DIM, OUT_DIM, OUT_DIM,
        cb1, cb2, dvec, 0, nullptr, nullptr, dec, nullptr, nullptr);
}

// round 12
// speedup vs baseline: 2.5845x; 1.1963x over previous
#include <cuda_runtime.h>
#include <cuda_fp16.h>
#include <cstdint>

#define IN_DIM  2048
#define HDIM    8192
#define OUT_DIM 512
#define NBATCH  4096

typedef __half fp16;

// ---------------- scratch (static __device__ per harness rules) ----------------
__device__ __align__(256) fp16 g_xhi [(size_t)NBATCH * IN_DIM];
__device__ __align__(256) fp16 g_xlo [(size_t)NBATCH * IN_DIM];
__device__ __align__(256) fp16 g_W1hi[(size_t)IN_DIM * HDIM];     // Ŵ1 = W1/s1
__device__ __align__(256) fp16 g_W1Thi[(size_t)HDIM * IN_DIM];
__device__ __align__(256) fp16 g_W2Thi[(size_t)OUT_DIM * HDIM];   // Ŵ2ᵀ = (W2/s2)ᵀ
__device__ __align__(256) fp16 g_z1hi[(size_t)NBATCH * HDIM];
__device__ __align__(256) fp16 g_zhi [(size_t)NBATCH * OUT_DIM];
__device__ __align__(256) fp16 g_zlo [(size_t)NBATCH * OUT_DIM];
__device__ __align__(256) float g_Mpart[(size_t)4 * IN_DIM * OUT_DIM];  // K-split partials
__device__ __align__(256) fp16 g_Mhi [(size_t)IN_DIM * OUT_DIM];  // M̂ = Ŵ1@Ŵ2
__device__ __align__(256) float g_dvec[IN_DIM];                   // db1@W1ᵀ + db2
__device__ int g_maskmode;

// ---------------- PTX helpers (compute_100-safe) ----------------
__device__ __forceinline__ uint32_t smem_u32(const void* p) {
    uint32_t a;
    asm("{ .reg .u64 t; cvta.to.shared.u64 t, %1; cvt.u32.u64 %0, t; }" : "=r"(a) : "l"(p));
    return a;
}
#define SWZ128(off) ((off) ^ (((off) >> 3) & 0x70))

__device__ __forceinline__ void cp16cp(uint32_t dst, const void* src) {
    asm volatile("cp.async.cg.shared.global [%0], [%1], 16;" :: "r"(dst), "l"(src));
}
#define CP_COMMIT() asm volatile("cp.async.commit_group;" ::: "memory")
#define CP_WAIT(n)  asm volatile("cp.async.wait_group %0;" :: "n"(n) : "memory")

__device__ __forceinline__ void ldsm4(uint32_t a, uint32_t& r0, uint32_t& r1,
                                      uint32_t& r2, uint32_t& r3) {
    asm volatile("ldmatrix.sync.aligned.m8n8.x4.shared.b16 {%0,%1,%2,%3}, [%4];"
                 : "=r"(r0), "=r"(r1), "=r"(r2), "=r"(r3) : "r"(a));
}

__device__ __forceinline__ void mma16816(float* d, const uint32_t* a, const uint32_t* b) {
    asm volatile("mma.sync.aligned.m16n8k16.row.col.f32.f16.f16.f32 "
        "{%0,%1,%2,%3}, {%4,%5,%6,%7}, {%8,%9}, {%0,%1,%2,%3};"
        : "+f"(d[0]), "+f"(d[1]), "+f"(d[2]), "+f"(d[3])
        : "r"(a[0]), "r"(a[1]), "r"(a[2]), "r"(a[3]), "r"(b[0]), "r"(b[1]));
}

// ---------------- mask dtype detection ----------------
__global__ void detect_mask_kernel(const unsigned int* __restrict__ m, int nwords) {
    __shared__ int ok[4];
    if (threadIdx.x < 4) ok[threadIdx.x] = 1;
    __syncthreads();
    for (int i = threadIdx.x; i < nwords; i += blockDim.x) {
        unsigned w = m[i];
        if (!(w == 0u || w == 1u))          atomicAnd(&ok[0], 0);
        if (!(w == 0u || w == 0x3F800000u)) atomicAnd(&ok[1], 0);
        unsigned lo = w & 0xFFFFu, hi = w >> 16;
        if (!((lo == 0u || lo == 0x3F80u) && (hi == 0u || hi == 0x3F80u))) atomicAnd(&ok[2], 0);
        if (!((lo == 0u || lo == 0x3C00u) && (hi == 0u || hi == 0x3C00u))) atomicAnd(&ok[3], 0);
    }
    __syncthreads();
    if (threadIdx.x == 0) {
        int mode = 0;
        if      (ok[0]) mode = 1;
        else if (ok[1]) mode = 2;
        else if (ok[2]) mode = 3;
        else if (ok[3]) mode = 4;
        g_maskmode = mode;
    }
}

__device__ __forceinline__ int read_mask(const void* p, long i, int mode) {
    switch (mode) {
        case 1:  return ((const int*)p)[i] != 0;
        case 2:  return ((const float*)p)[i] != 0.0f;
        case 3:  return ((const unsigned short*)p)[i] != 0;
        case 4:  return ((const unsigned short*)p)[i] != 0;
        default: return ((const unsigned char*)p)[i] != 0;
    }
}

__device__ __forceinline__ void split2h(float v, fp16& h, fp16& l) {
    h = __float2half(v);
    l = __float2half(v - __half2float(h));
}

// ---------------- split x (vectorized: 4 elems/thread) ----------------
__global__ void split_kernel(const float4* __restrict__ src, __half2* __restrict__ hi,
                             __half2* __restrict__ lo, size_t n4) {
    size_t i = (size_t)blockIdx.x * blockDim.x + threadIdx.x;
    if (i < n4) {
        float4 v = src[i];
        fp16 h0, l0, h1, l1, h2, l2, h3, l3;
        split2h(v.x, h0, l0); split2h(v.y, h1, l1);
        split2h(v.z, h2, l2); split2h(v.w, h3, l3);
        hi[2 * i]     = __halves2half2(h0, h1);
        hi[2 * i + 1] = __halves2half2(h2, h3);
        lo[2 * i]     = __halves2half2(l0, l1);
        lo[2 * i + 1] = __halves2half2(l2, l3);
    }
}

// ---------------- dequant + scale-factor + transpose (outputs nullable) -----
// vhat = (mask ? cb[idx] : wf) / s, s = cb[3] (exact for codebook entries).
__global__ void dequant_split_kernel(const int* __restrict__ idx, const void* __restrict__ mask,
                                     const float* __restrict__ wf, const float* __restrict__ cb,
                                     fp16* __restrict__ Whi,
                                     fp16* __restrict__ WThi,
                                     int R, int C) {
    __shared__ float tile[32][33];
    const int mode = g_maskmode;
    float s = __ldg(cb + 3);
    if (s == 0.0f) s = 1.0f;
    const int c0 = blockIdx.x * 32;
    const int r0 = blockIdx.y * 32;
    for (int rr = threadIdx.y; rr < 32; rr += 8) {
        long off = (long)(r0 + rr) * C + c0 + threadIdx.x;
        int  m = read_mask(mask, off, mode);
        float v = (m ? cb[idx[off]] : wf[off]) / s;   // exact for codebook
        if (Whi) Whi[off] = __float2half(v);
        tile[rr][threadIdx.x] = v;
    }
    __syncthreads();
    if (WThi) {
        for (int rr = threadIdx.y; rr < 32; rr += 8) {
            float v = tile[threadIdx.x][rr];
            long off = (long)(c0 + rr) * R + r0 + threadIdx.x;
            WThi[off] = __float2half(v);
        }
    }
}

// ---------------- K-split reduce + fp16 for M (hi only) ----------------
__global__ void reduce_split_kernel(const float* __restrict__ part,
                                    fp16* __restrict__ Mhi, size_t n) {
    size_t i = (size_t)blockIdx.x * blockDim.x + threadIdx.x;
    if (i < n) {
        float v = part[i] + part[i + n] + part[i + 2 * n] + part[i + 3 * n];
        Mhi[i] = __float2half(v);
    }
}

// ---------------- dvec = s1*(db1 @ Ŵ1ᵀ) + db2 ----------------
__global__ void dvec_kernel(const fp16* __restrict__ W1hi,
                            const float* __restrict__ db1, const float* __restrict__ db2,
                            const float* __restrict__ cb1, float* __restrict__ dvec) {
    __shared__ float red[256];
    const int j = blockIdx.x;
    float s = __ldg(cb1 + 3);
    if (s == 0.0f) s = 1.0f;
    float sum = 0.0f;
    const size_t base = (size_t)j * HDIM;
    for (int h = threadIdx.x; h < HDIM; h += 256)
        sum += __half2float(W1hi[base + h]) * __ldg(db1 + h);
    red[threadIdx.x] = sum;
    __syncthreads();
    for (int st = 128; st > 0; st >>= 1) {
        if (threadIdx.x < st) red[threadIdx.x] += red[threadIdx.x + st];
        __syncthreads();
    }
    if (threadIdx.x == 0) dvec[j] = fmaf(s, red[0], __ldg(db2 + j));
}

// ---------------- c19 activation ----------------
__device__ __forceinline__ float c19f(float x, float craw, float rhoraw) {
    float c   = fmaxf(craw, 0.1f);
    float rho = fmaxf(rhoraw, 0.0f);
    float L   = 6.0f * c;
    float s   = x / c;
    float n   = floorf(s);
    float t   = s - n;
    float h   = t * (1.0f - t);
    float sgn = (fmodf(n, 2.0f) == 0.0f) ? 1.0f : -1.0f;
    float interior = c * (sgn * h + rho * h * h);
    return (x >= L) ? (x - L) : ((x <= -L) ? (x + L) : interior);
}

// ---------------- fp16 multi-product GEMM ----------------
// acc = Ahi*Bhi (+ Alo*Bhi if PA==2) (+ Ahi*Blo if PB==2)
// C = sa*sb*acc + bias (nullable). B K-major. Block 128 x (NI*32), 8 warps 2x4.
// gridDim.z = K-splits (partials at Cf + z*M*Nn). ldk = row stride of A and B.
#define BM 128
#define BKK 32

template<int NI, int PA, int PB, int NSTAGE>
__global__ void __launch_bounds__(256, 1)
gemm_fp16_kernel(const fp16* __restrict__ Ahi, const fp16* __restrict__ Alo,
                 const fp16* __restrict__ Bhi, const fp16* __restrict__ Blo,
                 int M, int Nn, int Klen, int ldk,
                 const float* __restrict__ cba, const float* __restrict__ cbb,
                 const float* __restrict__ bias, int epi,
                 const float* __restrict__ craw, const float* __restrict__ rho,
                 float* __restrict__ Cf, fp16* __restrict__ Chi, fp16* __restrict__ Clo) {
    constexpr int BN = NI * 32;
    constexpr int A_BYTES = BM * 64;
    constexpr int B_BYTES = BN * 64;
    constexpr int STAGE_BYTES = PA * A_BYTES + PB * B_BYTES;
    extern __shared__ char smem[];
    const uint32_t sbase = smem_u32(smem);
    const uint32_t tbase = (sbase + 1023u) & ~1023u;
    const int tid  = threadIdx.x;
    const int wid  = tid >> 5;
    const int lane = tid & 31;
    const int wm = wid & 1;
    const int wn = wid >> 1;

    const int m0 = blockIdx.y * BM;
    const int n0 = blockIdx.x * BN;
    const size_t kbase = (size_t)blockIdx.z * Klen;

    float sa = cba ? __ldg(cba + 3) : 1.0f;  if (sa == 0.0f) sa = 1.0f;
    float sb = cbb ? __ldg(cbb + 3) : 1.0f;  if (sb == 0.0f) sb = 1.0f;
    const float sc = sa * sb;

    uint32_t sAh[NSTAGE], sAl[NSTAGE], sBh[NSTAGE], sBl[NSTAGE];
#pragma unroll
    for (int s = 0; s < NSTAGE; s++) {
        uint32_t b = tbase + s * STAGE_BYTES;
        sAh[s] = b;
        sAl[s] = b + A_BYTES;                         // valid if PA==2
        sBh[s] = b + PA * A_BYTES;
        sBl[s] = b + PA * A_BYTES + B_BYTES;          // valid if PB==2
    }

    const int ITERS = Klen / BKK;

    float acc[4][NI][4];
#pragma unroll
    for (int i = 0; i < 4; i++)
#pragma unroll
        for (int j = 0; j < NI; j++)
#pragma unroll
            for (int r = 0; r < 4; r++) acc[i][j][r] = 0.0f;

    auto fill = [&](int kc) {
        const int s = kc % NSTAGE;
        const size_t k0 = kbase + (size_t)kc * BKK;
#pragma unroll
        for (int i = 0; i < 2; i++) {
            int ch = tid + i * 256;
            int r = ch >> 2, c = ch & 3;
            uint32_t so = SWZ128(r * 64 + c * 16);
            const char* pA = (const char*)(Ahi + (size_t)(m0 + r) * ldk + k0) + c * 16;
            cp16cp(sAh[s] + so, pA);
            if (PA == 2) {
                const char* pL = (const char*)(Alo + (size_t)(m0 + r) * ldk + k0) + c * 16;
                cp16cp(sAl[s] + so, pL);
            }
        }
#pragma unroll
        for (int i = 0; i < NI / 2; i++) {
            int ch = tid + i * 256;
            int r = ch >> 2, c = ch & 3;
            uint32_t so = SWZ128(r * 64 + c * 16);
            const char* pB = (const char*)(Bhi + (size_t)(n0 + r) * ldk + k0) + c * 16;
            cp16cp(sBh[s] + so, pB);
            if (PB == 2) {
                const char* pBl = (const char*)(Blo + (size_t)(n0 + r) * ldk + k0) + c * 16;
                cp16cp(sBl[s] + so, pBl);
            }
        }
    };

    // prologue
    for (int it = 0; it < NSTAGE - 1; it++) { fill(it); CP_COMMIT(); }

    for (int it = 0; it < ITERS; it++) {
        CP_WAIT(NSTAGE - 2);
        __syncthreads();
        if (it + NSTAGE - 1 < ITERS) fill(it + NSTAGE - 1);
        CP_COMMIT();

        const int s = it % NSTAGE;
#pragma unroll
        for (int kk = 0; kk < 2; kk++) {
            uint32_t afh[4][4], afl[4][4];
#pragma unroll
            for (int mi = 0; mi < 4; mi++) {
                int row = wm * 64 + mi * 16 + (lane & 15);
                int ch  = kk * 2 + (lane >> 4);
                uint32_t so = SWZ128(row * 64 + ch * 16);
                ldsm4(sAh[s] + so, afh[mi][0], afh[mi][1], afh[mi][2], afh[mi][3]);
                if (PA == 2)
                    ldsm4(sAl[s] + so, afl[mi][0], afl[mi][1], afl[mi][2], afl[mi][3]);
            }
            uint32_t bfh[NI][2], bfl[NI][2];
#pragma unroll
            for (int p = 0; p < NI / 2; p++) {
                int g   = lane >> 3;
                int row = wn * (NI * 8) + (p * 2 + (g >> 1)) * 8 + (lane & 7);
                int ch  = kk * 2 + (g & 1);
                uint32_t so = SWZ128(row * 64 + ch * 16);
                uint32_t r0, r1, r2, r3;
                ldsm4(sBh[s] + so, r0, r1, r2, r3);
                bfh[p * 2][0] = r0;  bfh[p * 2][1] = r1;
                bfh[p * 2 + 1][0] = r2; bfh[p * 2 + 1][1] = r3;
                if (PB == 2) {
                    ldsm4(sBl[s] + so, r0, r1, r2, r3);
                    bfl[p * 2][0] = r0;  bfl[p * 2][1] = r1;
                    bfl[p * 2 + 1][0] = r2; bfl[p * 2 + 1][1] = r3;
                }
            }
#pragma unroll
            for (int mi = 0; mi < 4; mi++)
#pragma unroll
                for (int ni = 0; ni < NI; ni++)
                    mma16816(acc[mi][ni], afh[mi], bfh[ni]);
            if (PA == 2) {
#pragma unroll
                for (int mi = 0; mi < 4; mi++)
#pragma unroll
                    for (int ni = 0; ni < NI; ni++)
                        mma16816(acc[mi][ni], afl[mi], bfh[ni]);
            }
            if (PB == 2) {
#pragma unroll
                for (int mi = 0; mi < 4; mi++)
#pragma unroll
                    for (int ni = 0; ni < NI; ni++)
                        mma16816(acc[mi][ni], afh[mi], bfl[ni]);
            }
        }
    }

    // ---------------- epilogue: scale + bias (+c19) + outputs ----------------
    float* CfZ = Cf ? Cf + (size_t)blockIdx.z * M * Nn : nullptr;
#pragma unroll
    for (int ni = 0; ni < NI; ni++) {
        const int n = n0 + wn * (NI * 8) + ni * 8 + 2 * (lane & 3);
        const float bv0 = bias ? __ldg(bias + n)     : 0.0f;
        const float bv1 = bias ? __ldg(bias + n + 1) : 0.0f;
        float c0 = 0, c1 = 0, r0 = 0, r1 = 0;
        if (epi) {
            c0 = __ldg(craw + n);  c1 = __ldg(craw + n + 1);
            r0 = __ldg(rho + n);   r1 = __ldg(rho + n + 1);
        }
#pragma unroll
        for (int mi = 0; mi < 4; mi++) {
#pragma unroll
            for (int h = 0; h < 2; h++) {
                const int m = m0 + wm * 64 + mi * 16 + (lane >> 2) + h * 8;
                float v0 = fmaf(sc, acc[mi][ni][2 * h],     bv0);
                float v1 = fmaf(sc, acc[mi][ni][2 * h + 1], bv1);
                if (epi) { v0 = c19f(v0, c0, r0); v1 = c19f(v1, c1, r1); }
                const size_t off = (size_t)m * Nn + n;
                if (CfZ) *(float2*)(CfZ + off) = make_float2(v0, v1);
                if (Chi) {
                    fp16 h0, l0, h1, l1;
                    split2h(v0, h0, l0); split2h(v1, h1, l1);
                    *(__half2*)(Chi + off) = __halves2half2(h0, h1);
                    if (Clo) *(__half2*)(Clo + off) = __halves2half2(l0, l1);
                }
            }
        }
    }
}

#define SMEM_CFG(NI, PA, PB, NSTAGE) \
    (1024 + (NSTAGE) * ((PA) * BM * 64 + (PB) * (NI) * 32 * 64))

// ---------------- launch ----------------
extern "C" void kernel_launch(void* const* d_in, const int* in_sizes, int n_in,
                              void* d_out, int out_size) {
    const float* x    = (const float*)d_in[0];
    const float* cb1  = (const float*)d_in[1];
    const float* cb2  = (const float*)d_in[2];
    const float* W1f  = (const float*)d_in[3];
    const float* W2f  = (const float*)d_in[4];
    const float* b1   = (const float*)d_in[5];
    const float* b2   = (const float*)d_in[6];
    const float* db1  = (const float*)d_in[7];
    const float* db2  = (const float*)d_in[8];
    const float* craw = (const float*)d_in[9];
    const float* rraw = (const float*)d_in[10];
    const int*   W1i  = (const int*)d_in[11];
    const int*   W2i  = (const int*)d_in[12];
    const void*  W1m  = d_in[13];
    const void*  W2m  = d_in[14];

    fp16 *xhi, *xlo, *W1hi, *W1Thi, *W2Thi;
    fp16 *z1hi, *zhi, *zlo, *Mhi;
    float *Mpart, *dvec;
    cudaGetSymbolAddress((void**)&xhi,  g_xhi);   cudaGetSymbolAddress((void**)&xlo,  g_xlo);
    cudaGetSymbolAddress((void**)&W1hi, g_W1hi);
    cudaGetSymbolAddress((void**)&W1Thi,g_W1Thi);
    cudaGetSymbolAddress((void**)&W2Thi,g_W2Thi);
    cudaGetSymbolAddress((void**)&z1hi, g_z1hi);
    cudaGetSymbolAddress((void**)&zhi,  g_zhi);   cudaGetSymbolAddress((void**)&zlo,  g_zlo);
    cudaGetSymbolAddress((void**)&Mpart,g_Mpart);
    cudaGetSymbolAddress((void**)&Mhi,  g_Mhi);
    cudaGetSymbolAddress((void**)&dvec, g_dvec);

    float* dec = (float*)d_out;
    float* z   = (float*)d_out + (size_t)NBATCH * IN_DIM;

    cudaFuncSetAttribute((const void*)gemm_fp16_kernel<8,2,1,4>,
                         cudaFuncAttributeMaxDynamicSharedMemorySize, SMEM_CFG(8,2,1,4));
    cudaFuncSetAttribute((const void*)gemm_fp16_kernel<4,1,1,5>,
                         cudaFuncAttributeMaxDynamicSharedMemorySize, SMEM_CFG(4,1,1,5));
    cudaFuncSetAttribute((const void*)gemm_fp16_kernel<4,2,1,4>,
                         cudaFuncAttributeMaxDynamicSharedMemorySize, SMEM_CFG(4,2,1,4));

    // 1. mask dtype probe
    detect_mask_kernel<<<1, 256>>>((const unsigned int*)W1m, 4096);

    // 2. split x; dequant (scaled by 1/cb[3])
    {
        size_t n4 = (size_t)NBATCH * IN_DIM / 4;
        split_kernel<<<(unsigned)((n4 + 255) / 256), 256>>>(
            (const float4*)x, (__half2*)xhi, (__half2*)xlo, n4);
    }
    dequant_split_kernel<<<dim3(HDIM / 32, IN_DIM / 32), dim3(32, 8)>>>(
        W1i, W1m, W1f, cb1, W1hi, W1Thi, IN_DIM, HDIM);
    dequant_split_kernel<<<dim3(OUT_DIM / 32, HDIM / 32), dim3(32, 8)>>>(
        W2i, W2m, W2f, cb2, nullptr, W2Thi, HDIM, OUT_DIM);

    // 3. GM: M̂ = Ŵ1hi @ Ŵ2hi (1-product, K-split 4)   [2048 x 512], K=8192
    gemm_fp16_kernel<4,1,1,5><<<dim3(OUT_DIM / 128, IN_DIM / BM, 4), 256, SMEM_CFG(4,1,1,5)>>>(
        W1hi, nullptr, W2Thi, nullptr, IN_DIM, OUT_DIM, HDIM / 4, HDIM,
        nullptr, nullptr, nullptr, 0, nullptr, nullptr, Mpart, nullptr, nullptr);
    {
        size_t n = (size_t)IN_DIM * OUT_DIM;
        reduce_split_kernel<<<(unsigned)((n + 255) / 256), 256>>>(Mpart, Mhi, n);
    }

    // 4. dvec = s1*(db1 @ Ŵ1hiᵀ) + db2
    dvec_kernel<<<IN_DIM, 256>>>(W1hi, db1, db2, cb1, dvec);

    // 5. G1: z1 = c19(s1*(x @ Ŵ1) + b1)   2-product   [4096 x 8192], K=2048
    gemm_fp16_kernel<8,2,1,4><<<dim3(HDIM / 256, NBATCH / BM), 256, SMEM_CFG(8,2,1,4)>>>(
        xhi, xlo, W1Thi, nullptr, NBATCH, HDIM, IN_DIM, IN_DIM,
        cb1, nullptr, b1, 1, craw, rraw, nullptr, z1hi, nullptr);

    // 6. G2: z = s2*(z1hi @ Ŵ2) + b2      1-product   [4096 x 512], K=8192
    gemm_fp16_kernel<4,1,1,5><<<dim3(OUT_DIM / 128, NBATCH / BM), 256, SMEM_CFG(4,1,1,5)>>>(
        z1hi, nullptr, W2Thi, nullptr, NBATCH, OUT_DIM, HDIM, HDIM,
        cb2, nullptr, b2, 0, nullptr, nullptr, z, zhi, zlo);

    // 7. G5: dec = s1*s2*((zhi+zlo) @ M̂hiᵀ) + dvec  2-product  [4096 x 2048], K=512
    gemm_fp16_kernel<4,2,1,4><<<dim3(IN_DIM / 128, NBATCH / BM), 256, SMEM_CFG(4,2,1,4)>>>(
        zhi, zlo, Mhi, nullptr, NBATCH, IN_DIM, OUT_DIM, OUT_DIM,
        cb1, cb2, dvec, 0, nullptr, nullptr, dec, nullptr, nullptr);
}